// round 11
// baseline (speedup 1.0000x reference)
#include <cuda_runtime.h>
#include <cuda_bf16.h>
#include <math.h>
#include <stdint.h>

typedef __nv_bfloat16 bf16;

#define Bc 4
#define Hc 128
#define Wc 128
#define Cc 192
#define NHc 6
#define WSc 16
#define SSc 8
#define Nc 256
#define HDc 32
#define NPIX (Bc*Hc*Wc)            // 65536
#define ATT_SCALE 0.17677669529663687f

#define AP2 72      // A smem row stride (64 k + 8 pad) — 144B, conflict-free ldsm
#define BP2 72      // B smem row stride
#define QP 40       // attention smem row stride

// GEMM/conv dynamic smem: 3 stages of (128 x AP2 A + 64 x BP2 B) bf16
#define AS_ST (128*AP2*2)
#define BS_ST (64*BP2*2)
#define SMEMG (3*(AS_ST + BS_ST))   // 82944 bytes

// ---------------- scratch (device globals) -----------------------------------
__device__ bf16  g_xnb [NPIX*Cc];
__device__ bf16  g_qkvb[(size_t)NPIX*3*Cc];
__device__ bf16  g_atb [NPIX*Cc];
__device__ bf16  g_cv1b[NPIX*64];
__device__ bf16  g_cv2b[NPIX*Cc];
__device__ float g_y   [NPIX*Cc];
__device__ bf16  g_ynb [NPIX*Cc];
__device__ bf16  g_hb  [(size_t)NPIX*4*Cc];
__device__ float g_pp  [Bc*64*Cc];
__device__ float g_ca  [Bc*Cc];
__device__ bf16  g_btb [NHc*Nc*Nc];
__device__ bf16  g_wqkv [Cc*3*Cc];
__device__ bf16  g_wproj[Cc*Cc];
__device__ bf16  g_wfc1 [Cc*4*Cc];
__device__ bf16  g_wfc2 [4*Cc*Cc];
__device__ bf16  g_wc1  [9*Cc*64];
__device__ bf16  g_wc2  [9*64*Cc];

__device__ __forceinline__ float gelu_exact(float x) {
    return 0.5f * x * (1.f + erff(x * 0.70710678118654752f));
}

// ---------------- ptx helpers ------------------------------------------------
#define CP16(dst, src) asm volatile("cp.async.cg.shared.global [%0], [%1], 16;\n" :: "r"(dst), "l"(src))
#define CP16Z(dst, src, sz) asm volatile("cp.async.cg.shared.global [%0], [%1], 16, %2;\n" :: "r"(dst), "l"(src), "r"(sz))
#define CP_COMMIT asm volatile("cp.async.commit_group;\n")
#define CP_WAITG1 asm volatile("cp.async.wait_group 1;\n")

__device__ __forceinline__ void ldsm4(uint32_t* r, uint32_t a) {
    asm volatile("ldmatrix.sync.aligned.m8n8.x4.shared.b16 {%0,%1,%2,%3},[%4];"
        : "=r"(r[0]), "=r"(r[1]), "=r"(r[2]), "=r"(r[3]) : "r"(a));
}
__device__ __forceinline__ void ldsm4t(uint32_t* r, uint32_t a) {
    asm volatile("ldmatrix.sync.aligned.m8n8.x4.trans.shared.b16 {%0,%1,%2,%3},[%4];"
        : "=r"(r[0]), "=r"(r[1]), "=r"(r[2]), "=r"(r[3]) : "r"(a));
}
__device__ __forceinline__ void mma_bf16(float* c, const uint32_t* a, const uint32_t* b) {
    asm volatile(
        "mma.sync.aligned.m16n8k16.row.col.f32.bf16.bf16.f32 "
        "{%0,%1,%2,%3}, {%4,%5,%6,%7}, {%8,%9}, {%0,%1,%2,%3};\n"
        : "+f"(c[0]), "+f"(c[1]), "+f"(c[2]), "+f"(c[3])
        : "r"(a[0]), "r"(a[1]), "r"(a[2]), "r"(a[3]), "r"(b[0]), "r"(b[1]));
}
__device__ __forceinline__ uint32_t pkbf2(float a, float b) {
    __nv_bfloat162 t = __floats2bfloat162_rn(a, b);
    return *(uint32_t*)&t;
}

// ---------------- batched weight convert --------------------------------------
#define S0 110592
#define S1 36864
#define S2 147456
#define S3 147456
#define S4 110592
#define S5 110592
#define STOT (S0+S1+S2+S3+S4+S5)
__global__ void f2b_all(const float* __restrict__ a0, const float* __restrict__ a1,
                        const float* __restrict__ a2, const float* __restrict__ a3,
                        const float* __restrict__ a4, const float* __restrict__ a5,
                        bf16* o0, bf16* o1, bf16* o2, bf16* o3, bf16* o4, bf16* o5) {
    int i = blockIdx.x * 256 + threadIdx.x;
    if (i >= STOT) return;
    if (i < S0)                { o0[i] = __float2bfloat16(a0[i]); return; }
    i -= S0;
    if (i < S1)                { o1[i] = __float2bfloat16(a1[i]); return; }
    i -= S1;
    if (i < S2)                { o2[i] = __float2bfloat16(a2[i]); return; }
    i -= S2;
    if (i < S3)                { o3[i] = __float2bfloat16(a3[i]); return; }
    i -= S3;
    if (i < S4)                { o4[i] = __float2bfloat16(a4[i]); return; }
    i -= S4;
    o5[i] = __float2bfloat16(a5[i]);
}

__global__ void btb_kernel(const float* __restrict__ rpb, const int* __restrict__ rpi,
                           bf16* __restrict__ btb) {
    int idx = blockIdx.x * 256 + threadIdx.x;
    int h = idx >> 16;
    int qk = idx & 65535;
    btb[idx] = __float2bfloat16(rpb[rpi[qk]*NHc + h]);
}

// ---------------- LayerNorm: warp per token ----------------------------------
__global__ __launch_bounds__(256) void ln_kernel(
        const float* __restrict__ x, const float* __restrict__ g,
        const float* __restrict__ b, bf16* __restrict__ out) {
    int t = (blockIdx.x * 256 + threadIdx.x) >> 5;
    int lane = threadIdx.x & 31;
    const float* row = x + (size_t)t * Cc;
    float v[6], s = 0.f, ss = 0.f;
    #pragma unroll
    for (int i = 0; i < 6; i++) {
        v[i] = row[i*32 + lane];
        s += v[i]; ss += v[i]*v[i];
    }
    #pragma unroll
    for (int o = 16; o; o >>= 1) {
        s  += __shfl_xor_sync(0xffffffffu, s, o);
        ss += __shfl_xor_sync(0xffffffffu, ss, o);
    }
    float m = s * (1.f/Cc);
    float inv = rsqrtf(ss * (1.f/Cc) - m*m + 1e-5f);
    #pragma unroll
    for (int i = 0; i < 6; i++) {
        int c = i*32 + lane;
        out[(size_t)t*Cc + c] = __float2bfloat16((v[i] - m)*inv*g[c] + b[c]);
    }
}

// ---------------- MMA compute on one 128x64x64 staged chunk ------------------
__device__ __forceinline__ void mma_stage64(uint32_t ab, uint32_t bb,
        const uint32_t aoff[2][4], const uint32_t boff[4][2], float acc[2][4][4]) {
    #pragma unroll
    for (int kk = 0; kk < 4; kk++) {
        uint32_t af[2][4], bq[2][4];
        ldsm4(af[0], ab + aoff[0][kk]);
        ldsm4(af[1], ab + aoff[1][kk]);
        ldsm4t(bq[0], bb + boff[kk][0]);
        ldsm4t(bq[1], bb + boff[kk][1]);
        #pragma unroll
        for (int mi = 0; mi < 2; mi++) {
            mma_bf16(acc[mi][0], af[mi], &bq[0][0]);
            mma_bf16(acc[mi][1], af[mi], &bq[0][2]);
            mma_bf16(acc[mi][2], af[mi], &bq[1][0]);
            mma_bf16(acc[mi][3], af[mi], &bq[1][2]);
        }
    }
}

__device__ __forceinline__ void mk_mma_offs64(int wm, int wn, int lane,
        uint32_t aoff[2][4], uint32_t boff[4][2]) {
    #pragma unroll
    for (int mi = 0; mi < 2; mi++)
        #pragma unroll
        for (int kk = 0; kk < 4; kk++) {
            int r = wm*32 + mi*16 + (lane & 15);
            int ko = kk*16 + ((lane >> 4) << 3);
            aoff[mi][kk] = (uint32_t)((r*AP2 + ko) * 2);
        }
    #pragma unroll
    for (int kk = 0; kk < 4; kk++)
        #pragma unroll
        for (int nh = 0; nh < 2; nh++) {
            int krow = kk*16 + (lane & 7) + (lane & 8);
            int ncol = wn*32 + nh*16 + ((lane >> 4) << 3);
            boff[kk][nh] = (uint32_t)((krow*BP2 + ncol) * 2);
        }
}

// ---------------- GEMM: MODE 0 bf16; 1 gelu bf16; 2 fp32+res; 3 proj-combine -
// 128x64 tile, K in 64-wide chunks, 3-stage cp.async pipeline (dynamic smem).
template<int MODE, int GATHER, int K, int N>
__global__ __launch_bounds__(256, 2) void mma_gemm(
        const bf16* __restrict__ A, const bf16* __restrict__ W,
        const float* __restrict__ bias, void* __restrict__ Cout_,
        const float* __restrict__ Rres, const float* __restrict__ xres,
        const bf16* __restrict__ cv2b, const float* __restrict__ cab) {
    extern __shared__ __align__(16) bf16 smg[];
    constexpr int nk = K >> 6;
    int tid = threadIdx.x;
    int m0 = blockIdx.x * 128, n0 = blockIdx.y * 64;
    int warp = tid >> 5, lane = tid & 31;
    int wm = warp & 3, wn = warp >> 2;
    int g = lane >> 2, tg = lane & 3;

    // A-load: one row per thread (tid>>1), 4x16B groups at col base (tid&1)*32
    int rowA = tid >> 1;
    int kgA  = (tid & 1) * 32;
    int grow;
    if (GATHER) {
        int t = m0 + rowA; int n = t & 255, win = t >> 8;
        int b = win >> 6, wl = win & 63;
        int hh = (((wl >> 3) << 4) + (n >> 4) + SSc) & 127;
        int ww = (((wl & 7) << 4) + (n & 15) + SSc) & 127;
        grow = (b*Hc + hh)*Wc + ww;
    } else grow = m0 + rowA;
    const bf16* srcA = A + (size_t)grow*K + kgA;
    uint32_t dofA = (uint32_t)((rowA*AP2 + kgA) * 2);
    // B-load: krow = tid>>2 (0..63), 2x16B at n-groups (tid&3)*8 and +32
    int krB = tid >> 2, ngB = (tid & 3) * 8;
    const bf16* srcB = W + (size_t)krB*N + n0 + ngB;
    uint32_t dofB = (uint32_t)((krB*BP2 + ngB) * 2);

    uint32_t asb = (uint32_t)__cvta_generic_to_shared(smg);
    uint32_t bsb = asb + 3*AS_ST;
    uint32_t aoff[2][4], boff[4][2];
    mk_mma_offs64(wm, wn, lane, aoff, boff);

    float acc[2][4][4];
    #pragma unroll
    for (int a = 0; a < 2; a++)
        #pragma unroll
        for (int b = 0; b < 4; b++)
            #pragma unroll
            for (int c = 0; c < 4; c++) acc[a][b][c] = 0.f;

    auto loadAB = [&](int st, int k0) {
        uint32_t ab = asb + st*AS_ST, bb = bsb + st*BS_ST;
        #pragma unroll
        for (int j = 0; j < 4; j++) CP16(ab + dofA + j*16, srcA + k0 + j*8);
        CP16(bb + dofB, srcB + (size_t)k0*N);
        CP16(bb + dofB + 64, srcB + (size_t)k0*N + 32);
    };

    loadAB(0, 0); CP_COMMIT;
    if (nk > 1) loadAB(1, 64);
    CP_COMMIT;

    int sl = 0;
    for (int c = 0; c < nk; c++) {
        CP_WAITG1;
        __syncthreads();
        int nx = c + 2;
        int sn = sl + 2; if (sn >= 3) sn -= 3;
        if (nx < nk) loadAB(sn, nx*64);
        CP_COMMIT;
        mma_stage64(asb + sl*AS_ST, bsb + sl*BS_ST, aoff, boff, acc);
        if (++sl == 3) sl = 0;
    }

    #pragma unroll
    for (int mi = 0; mi < 2; mi++) {
        #pragma unroll
        for (int nj = 0; nj < 4; nj++) {
            int r1 = m0 + wm*32 + mi*16 + g;
            int r2 = r1 + 8;
            int cg = n0 + wn*32 + nj*8 + tg*2;
            float b0 = bias[cg], b1 = bias[cg+1];
            float v00 = acc[mi][nj][0] + b0, v01 = acc[mi][nj][1] + b1;
            float v10 = acc[mi][nj][2] + b0, v11 = acc[mi][nj][3] + b1;
            if (MODE == 0) {
                bf16* C = (bf16*)Cout_;
                *(__nv_bfloat162*)(C + (size_t)r1*N + cg) = __floats2bfloat162_rn(v00, v01);
                *(__nv_bfloat162*)(C + (size_t)r2*N + cg) = __floats2bfloat162_rn(v10, v11);
            } else if (MODE == 1) {
                bf16* C = (bf16*)Cout_;
                *(__nv_bfloat162*)(C + (size_t)r1*N + cg) =
                    __floats2bfloat162_rn(gelu_exact(v00), gelu_exact(v01));
                *(__nv_bfloat162*)(C + (size_t)r2*N + cg) =
                    __floats2bfloat162_rn(gelu_exact(v10), gelu_exact(v11));
            } else if (MODE == 2) {
                float* C = (float*)Cout_;
                float2 ra = *(const float2*)(Rres + (size_t)r1*N + cg);
                float2 rb2 = *(const float2*)(Rres + (size_t)r2*N + cg);
                *(float2*)(C + (size_t)r1*N + cg) = make_float2(v00+ra.x, v01+ra.y);
                *(float2*)(C + (size_t)r2*N + cg) = make_float2(v10+rb2.x, v11+rb2.y);
            } else {
                float* Y = (float*)Cout_;
                int rr[2] = {r1, r2};
                float vv[2][2] = {{v00, v01}, {v10, v11}};
                #pragma unroll
                for (int q = 0; q < 2; q++) {
                    int t = rr[q];
                    int n = t & 255, win = t >> 8;
                    int b = win >> 6, wl = win & 63;
                    int hh = ((wl >> 3) << 4) + (n >> 4);
                    int ww = ((wl & 7) << 4) + (n & 15);
                    int oh = (hh + SSc) & 127, ow = (ww + SSc) & 127;
                    size_t p = (size_t)((b*Hc + oh)*Wc + ow);
                    float2 xv = *(const float2*)(xres + p*Cc + cg);
                    float2 cav = *(const float2*)(cab + b*Cc + cg);
                    float2 cvv = __bfloat1622float2(*(const __nv_bfloat162*)(cv2b + p*Cc + cg));
                    *(float2*)(Y + p*Cc + cg) = make_float2(
                        xv.x + vv[q][0] + cvv.x*cav.x*0.01f,
                        xv.y + vv[q][1] + cvv.y*cav.y*0.01f);
                }
            }
        }
    }
}

// ---------------- 3x3 conv (implicit GEMM, 64-wide chunks) --------------------
template<int MODE, int Cin, int Cout>
__global__ __launch_bounds__(256, 2) void mma_conv(
        const bf16* __restrict__ X, const bf16* __restrict__ Wt,
        const float* __restrict__ bias, bf16* __restrict__ Y) {
    extern __shared__ __align__(16) bf16 smg[];
    constexpr int CCH = Cin >> 6;        // 64-channel blocks per tap (3 or 1)
    constexpr int nk = 9 * CCH;
    int bi = blockIdx.x;
    int b = bi >> 7, h = bi & 127;
    int n0 = blockIdx.y * 64;
    int tid = threadIdx.x;
    int warp = tid >> 5, lane = tid & 31;
    int wm = warp & 3, wn = warp >> 2;
    int g = lane >> 2, tg = lane & 3;

    // A-load: one row per thread, 4x16B at col base (tid&1)*32
    int rowA = tid >> 1;
    int kgA  = (tid & 1) * 32;
    uint32_t dofA = (uint32_t)((rowA*AP2 + kgA) * 2);
    const bf16* rowbase[3];
    bool okH[3];
    #pragma unroll
    for (int d = 0; d < 3; d++) {
        int ih = h + d - 1;
        okH[d] = (ih >= 0 && ih < Hc);
        int ihc = min(max(ih, 0), Hc-1);
        rowbase[d] = X + (size_t)((b*Hc + ihc)*Wc) * Cin + kgA;
    }
    int iwc[3]; bool okW[3];
    #pragma unroll
    for (int d = 0; d < 3; d++) {
        int iw = rowA + d - 1;
        okW[d] = (iw >= 0 && iw < Wc);
        iwc[d] = min(max(iw, 0), Wc-1);
    }
    // B-load: krow = tid>>2, 2x16B at n-groups (tid&3)*8 and +32
    int krB = tid >> 2, ngB = (tid & 3) * 8;
    const bf16* srcB = Wt + (size_t)krB*Cout + n0 + ngB;
    uint32_t dofB = (uint32_t)((krB*BP2 + ngB) * 2);

    uint32_t asb = (uint32_t)__cvta_generic_to_shared(smg);
    uint32_t bsb = asb + 3*AS_ST;
    uint32_t aoff[2][4], boff[4][2];
    mk_mma_offs64(wm, wn, lane, aoff, boff);

    float acc[2][4][4];
    #pragma unroll
    for (int a = 0; a < 2; a++)
        #pragma unroll
        for (int bb = 0; bb < 4; bb++)
            #pragma unroll
            for (int c = 0; c < 4; c++) acc[a][bb][c] = 0.f;

    auto loadAB = [&](int st, int chunk) {
        int tap = chunk / CCH;               // compile-time divisor
        int ci0 = (chunk - tap*CCH) * 64;
        int dh = tap/3, dw = tap - dh*3;
        uint32_t ab = asb + st*AS_ST, bb = bsb + st*BS_ST;
        int sz = (okH[dh] && okW[dw]) ? 16 : 0;
        const bf16* src = rowbase[dh] + (size_t)iwc[dw]*Cin + ci0;
        #pragma unroll
        for (int j = 0; j < 4; j++) CP16Z(ab + dofA + j*16, src + j*8, sz);
        const bf16* sb = srcB + (size_t)chunk*64*Cout;
        CP16(bb + dofB, sb);
        CP16(bb + dofB + 64, sb + 32);
    };

    loadAB(0, 0); CP_COMMIT;
    loadAB(1, 1); CP_COMMIT;

    int sl = 0;
    for (int c = 0; c < nk; c++) {
        CP_WAITG1;
        __syncthreads();
        int nx = c + 2;
        int sn = sl + 2; if (sn >= 3) sn -= 3;
        if (nx < nk) loadAB(sn, nx);
        CP_COMMIT;
        mma_stage64(asb + sl*AS_ST, bsb + sl*BS_ST, aoff, boff, acc);
        if (++sl == 3) sl = 0;
    }

    #pragma unroll
    for (int mi = 0; mi < 2; mi++) {
        #pragma unroll
        for (int nj = 0; nj < 4; nj++) {
            int p1 = (b*Hc + h)*Wc + wm*32 + mi*16 + g;
            int p2 = p1 + 8;
            int cg = n0 + wn*32 + nj*8 + tg*2;
            float b0 = bias[cg], b1 = bias[cg+1];
            float v00 = acc[mi][nj][0] + b0, v01 = acc[mi][nj][1] + b1;
            float v10 = acc[mi][nj][2] + b0, v11 = acc[mi][nj][3] + b1;
            if (MODE == 1) {
                v00 = gelu_exact(v00); v01 = gelu_exact(v01);
                v10 = gelu_exact(v10); v11 = gelu_exact(v11);
            }
            *(__nv_bfloat162*)(Y + (size_t)p1*Cout + cg) = __floats2bfloat162_rn(v00, v01);
            *(__nv_bfloat162*)(Y + (size_t)p2*Cout + cg) = __floats2bfloat162_rn(v10, v11);
        }
    }
}

// ---------------- pool + channel attention -----------------------------------
__global__ void pool_kernel(const bf16* __restrict__ cv2b, float* __restrict__ pp) {
    int blk = blockIdx.x;
    int b = blk >> 6, chunk = blk & 63;
    int c = threadIdx.x;
    float s = 0.f;
    int base = b*16384 + chunk*256;
    for (int p = 0; p < 256; p++) s += __bfloat162float(cv2b[(size_t)(base + p)*Cc + c]);
    pp[blk*Cc + c] = s;
}

__global__ void ca_kernel(const float* __restrict__ pp,
                          const float* __restrict__ w1, const float* __restrict__ b1,
                          const float* __restrict__ w2, const float* __restrict__ b2,
                          float* __restrict__ ca) {
    __shared__ float pooled[Bc*Cc];
    __shared__ float t1[Bc*6];
    int tid = threadIdx.x;
    for (int i = tid; i < Bc*Cc; i += 256) {
        int b = i / Cc, c = i % Cc;
        float s = 0.f;
        for (int j = 0; j < 64; j++) s += pp[(b*64 + j)*Cc + c];
        pooled[i] = s * (1.f/16384.f);
    }
    __syncthreads();
    if (tid < Bc*6) {
        int b = tid / 6, j = tid % 6;
        float s = b1[j];
        for (int c = 0; c < Cc; c++) s += pooled[b*Cc + c] * w1[c*6 + j];
        t1[tid] = fmaxf(s, 0.f);
    }
    __syncthreads();
    for (int i = tid; i < Bc*Cc; i += 256) {
        int b = i / Cc, c = i % Cc;
        float s = b2[c];
        #pragma unroll
        for (int j = 0; j < 6; j++) s += t1[b*6 + j] * w2[j*Cc + c];
        ca[i] = 1.f / (1.f + expf(-s));
    }
}

// ---------------- flash window attention via tensor-core MMA ------------------
__global__ __launch_bounds__(256) void attn_mma(
        const bf16* __restrict__ qkvb, const bf16* __restrict__ btb,
        bf16* __restrict__ out) {
    extern __shared__ __align__(16) bf16 smA[];
    bf16* Qs = smA;
    bf16* Ks = smA + 256*QP;
    bf16* Vs = smA + 2*256*QP;
    int win = blockIdx.x, h = blockIdx.y;
    int tid = threadIdx.x;
    int warp = tid >> 5, lane = tid & 31;
    int g = lane >> 2, tg = lane & 3;
    int m0 = warp * 32;

    {
        const uint4* src = (const uint4*)(qkvb + (size_t)(win*Nc + tid)*576 + h*HDc);
        uint4* qd = (uint4*)(Qs + tid*QP);
        uint4* kd = (uint4*)(Ks + tid*QP);
        uint4* vd = (uint4*)(Vs + tid*QP);
        #pragma unroll
        for (int i = 0; i < 4; i++) {
            qd[i] = src[i];
            kd[i] = src[i + 24];
            vd[i] = src[i + 48];
        }
    }
    __syncthreads();

    uint32_t qf[2][2][4];
    #pragma unroll
    for (int mi = 0; mi < 2; mi++)
        #pragma unroll
        for (int ks = 0; ks < 2; ks++) {
            int r = m0 + mi*16 + (lane & 15);
            int kofs = ks*16 + ((lane >> 4) << 3);
            ldsm4(qf[mi][ks], (uint32_t)__cvta_generic_to_shared(Qs + r*QP + kofs));
        }

    const bf16* cb = btb + ((size_t)h << 16);

    int wl = win & 63;
    bool er = (wl >> 3) == 7, ec = (wl & 7) == 7;
    bool edge = er || ec;
    int lq[2][2];
    #pragma unroll
    for (int mi = 0; mi < 2; mi++)
        #pragma unroll
        for (int rh = 0; rh < 2; rh++) {
            int q = m0 + mi*16 + g + rh*8;
            int rc = er ? (((q >> 4) < 8) ? 1 : 2) : 0;
            int cc = ec ? (((q & 15) < 8) ? 1 : 2) : 0;
            lq[mi][rh] = rc*3 + cc;
        }

    float mx[2][2], lsum[2][2];
    float o[2][4][4];
    #pragma unroll
    for (int mi = 0; mi < 2; mi++)
        #pragma unroll
        for (int rh = 0; rh < 2; rh++) { mx[mi][rh] = -1e30f; lsum[mi][rh] = 0.f; }
    #pragma unroll
    for (int mi = 0; mi < 2; mi++)
        #pragma unroll
        for (int nt = 0; nt < 4; nt++)
            #pragma unroll
            for (int e = 0; e < 4; e++) o[mi][nt][e] = 0.f;

    for (int c0 = 0; c0 < Nc; c0 += 32) {
        float s[2][4][4];
        #pragma unroll
        for (int mi = 0; mi < 2; mi++)
            #pragma unroll
            for (int nj = 0; nj < 4; nj++)
                #pragma unroll
                for (int e = 0; e < 4; e++) s[mi][nj][e] = 0.f;

        #pragma unroll
        for (int ks = 0; ks < 2; ks++) {
            uint32_t kf[2][4];
            #pragma unroll
            for (int np = 0; np < 2; np++) {
                int n = c0 + np*16 + (lane & 7) + ((lane >> 4) << 3);
                int kc = ks*16 + ((lane >> 3) & 1)*8;
                ldsm4(kf[np], (uint32_t)__cvta_generic_to_shared(Ks + n*QP + kc));
            }
            #pragma unroll
            for (int mi = 0; mi < 2; mi++) {
                mma_bf16(s[mi][0], qf[mi][ks], &kf[0][0]);
                mma_bf16(s[mi][1], qf[mi][ks], &kf[0][2]);
                mma_bf16(s[mi][2], qf[mi][ks], &kf[1][0]);
                mma_bf16(s[mi][3], qf[mi][ks], &kf[1][2]);
            }
        }

        int lk[4][2];
        if (edge) {
            #pragma unroll
            for (int nj = 0; nj < 4; nj++)
                #pragma unroll
                for (int e = 0; e < 2; e++) {
                    int kcol = c0 + nj*8 + tg*2 + e;
                    int rc = er ? (((kcol >> 4) < 8) ? 1 : 2) : 0;
                    int cc = ec ? (((kcol & 15) < 8) ? 1 : 2) : 0;
                    lk[nj][e] = rc*3 + cc;
                }
        }
        #pragma unroll
        for (int mi = 0; mi < 2; mi++) {
            int row0 = m0 + mi*16 + g;
            #pragma unroll
            for (int nj = 0; nj < 4; nj++) {
                int col = c0 + nj*8 + tg*2;
                float2 b0 = __bfloat1622float2(*(const __nv_bfloat162*)(cb + (size_t)row0*Nc + col));
                float2 b1 = __bfloat1622float2(*(const __nv_bfloat162*)(cb + (size_t)(row0+8)*Nc + col));
                s[mi][nj][0] = s[mi][nj][0]*ATT_SCALE + b0.x;
                s[mi][nj][1] = s[mi][nj][1]*ATT_SCALE + b0.y;
                s[mi][nj][2] = s[mi][nj][2]*ATT_SCALE + b1.x;
                s[mi][nj][3] = s[mi][nj][3]*ATT_SCALE + b1.y;
                if (edge) {
                    s[mi][nj][0] += (lq[mi][0] == lk[nj][0]) ? 0.f : -100.f;
                    s[mi][nj][1] += (lq[mi][0] == lk[nj][1]) ? 0.f : -100.f;
                    s[mi][nj][2] += (lq[mi][1] == lk[nj][0]) ? 0.f : -100.f;
                    s[mi][nj][3] += (lq[mi][1] == lk[nj][1]) ? 0.f : -100.f;
                }
            }
            #pragma unroll
            for (int rh = 0; rh < 2; rh++) {
                int e0 = rh*2;
                float m_ = fmaxf(fmaxf(s[mi][0][e0], s[mi][0][e0+1]),
                                 fmaxf(s[mi][1][e0], s[mi][1][e0+1]));
                m_ = fmaxf(m_, fmaxf(fmaxf(s[mi][2][e0], s[mi][2][e0+1]),
                                     fmaxf(s[mi][3][e0], s[mi][3][e0+1])));
                m_ = fmaxf(m_, __shfl_xor_sync(0xffffffffu, m_, 1));
                m_ = fmaxf(m_, __shfl_xor_sync(0xffffffffu, m_, 2));
                float newm = fmaxf(mx[mi][rh], m_);
                float sc = __expf(mx[mi][rh] - newm);
                mx[mi][rh] = newm;
                float ps = 0.f;
                #pragma unroll
                for (int nj = 0; nj < 4; nj++) {
                    float p0 = __expf(s[mi][nj][e0]   - newm);
                    float p1 = __expf(s[mi][nj][e0+1] - newm);
                    s[mi][nj][e0] = p0; s[mi][nj][e0+1] = p1;
                    ps += p0 + p1;
                }
                ps += __shfl_xor_sync(0xffffffffu, ps, 1);
                ps += __shfl_xor_sync(0xffffffffu, ps, 2);
                lsum[mi][rh] = lsum[mi][rh]*sc + ps;
                #pragma unroll
                for (int nt = 0; nt < 4; nt++) {
                    o[mi][nt][e0]   *= sc;
                    o[mi][nt][e0+1] *= sc;
                }
            }
        }

        #pragma unroll
        for (int ks2 = 0; ks2 < 2; ks2++) {
            uint32_t vf[2][4];
            int krow = c0 + ks2*16 + (lane & 7) + (lane & 8);
            #pragma unroll
            for (int dp = 0; dp < 2; dp++)
                ldsm4t(vf[dp], (uint32_t)__cvta_generic_to_shared(
                    Vs + krow*QP + dp*16 + ((lane >> 4) << 3)));
            #pragma unroll
            for (int mi = 0; mi < 2; mi++) {
                uint32_t af[4];
                af[0] = pkbf2(s[mi][2*ks2][0],   s[mi][2*ks2][1]);
                af[1] = pkbf2(s[mi][2*ks2][2],   s[mi][2*ks2][3]);
                af[2] = pkbf2(s[mi][2*ks2+1][0], s[mi][2*ks2+1][1]);
                af[3] = pkbf2(s[mi][2*ks2+1][2], s[mi][2*ks2+1][3]);
                mma_bf16(o[mi][0], af, &vf[0][0]);
                mma_bf16(o[mi][1], af, &vf[0][2]);
                mma_bf16(o[mi][2], af, &vf[1][0]);
                mma_bf16(o[mi][3], af, &vf[1][2]);
            }
        }
    }

    #pragma unroll
    for (int mi = 0; mi < 2; mi++) {
        #pragma unroll
        for (int rh = 0; rh < 2; rh++) {
            float inv = 1.f / lsum[mi][rh];
            int row = win*Nc + m0 + mi*16 + g + rh*8;
            bf16* orow = out + (size_t)row*Cc + h*HDc;
            #pragma unroll
            for (int nt = 0; nt < 4; nt++) {
                *(__nv_bfloat162*)(orow + nt*8 + tg*2) =
                    __floats2bfloat162_rn(o[mi][nt][rh*2]*inv, o[mi][nt][rh*2+1]*inv);
            }
        }
    }
}

// ---------------- launch -----------------------------------------------------
extern "C" void kernel_launch(void* const* d_in, const int* in_sizes, int n_in,
                              void* d_out, int out_size) {
    const float* x     = (const float*)d_in[0];
    const float* qkv_w = (const float*)d_in[1];
    const float* qkv_b = (const float*)d_in[2];
    const float* proj_w= (const float*)d_in[3];
    const float* proj_b= (const float*)d_in[4];
    const float* rpb   = (const float*)d_in[5];
    const float* n1w   = (const float*)d_in[6];
    const float* n1b   = (const float*)d_in[7];
    const float* n2w   = (const float*)d_in[8];
    const float* n2b   = (const float*)d_in[9];
    const float* c1w   = (const float*)d_in[10];
    const float* c1b   = (const float*)d_in[11];
    const float* c2w   = (const float*)d_in[12];
    const float* c2b   = (const float*)d_in[13];
    const float* ca1w  = (const float*)d_in[14];
    const float* ca1b  = (const float*)d_in[15];
    const float* ca2w  = (const float*)d_in[16];
    const float* ca2b  = (const float*)d_in[17];
    const float* fc1w  = (const float*)d_in[18];
    const float* fc1b  = (const float*)d_in[19];
    const float* fc2w  = (const float*)d_in[20];
    const float* fc2b  = (const float*)d_in[21];
    const int*   rpi   = (const int*)d_in[22];
    float* out = (float*)d_out;

    bf16 *xnb, *qkvb, *atb, *cv1b, *cv2b, *ynb, *hb, *btb;
    bf16 *wqkv, *wproj, *wfc1, *wfc2, *wc1, *wc2;
    float *y, *pp, *cab;
    cudaGetSymbolAddress((void**)&xnb,  g_xnb);
    cudaGetSymbolAddress((void**)&qkvb, g_qkvb);
    cudaGetSymbolAddress((void**)&atb,  g_atb);
    cudaGetSymbolAddress((void**)&cv1b, g_cv1b);
    cudaGetSymbolAddress((void**)&cv2b, g_cv2b);
    cudaGetSymbolAddress((void**)&y,    g_y);
    cudaGetSymbolAddress((void**)&ynb,  g_ynb);
    cudaGetSymbolAddress((void**)&hb,   g_hb);
    cudaGetSymbolAddress((void**)&pp,   g_pp);
    cudaGetSymbolAddress((void**)&cab,  g_ca);
    cudaGetSymbolAddress((void**)&btb,  g_btb);
    cudaGetSymbolAddress((void**)&wqkv, g_wqkv);
    cudaGetSymbolAddress((void**)&wproj,g_wproj);
    cudaGetSymbolAddress((void**)&wfc1, g_wfc1);
    cudaGetSymbolAddress((void**)&wfc2, g_wfc2);
    cudaGetSymbolAddress((void**)&wc1,  g_wc1);
    cudaGetSymbolAddress((void**)&wc2,  g_wc2);

    static bool attr_set = false;
    if (!attr_set) {
        cudaFuncSetAttribute(attn_mma, cudaFuncAttributeMaxDynamicSharedMemorySize,
                             3*256*QP*sizeof(bf16));
        cudaFuncSetAttribute(mma_gemm<0,1,Cc,3*Cc>, cudaFuncAttributeMaxDynamicSharedMemorySize, SMEMG);
        cudaFuncSetAttribute(mma_gemm<3,0,Cc,Cc>,   cudaFuncAttributeMaxDynamicSharedMemorySize, SMEMG);
        cudaFuncSetAttribute(mma_gemm<1,0,Cc,4*Cc>, cudaFuncAttributeMaxDynamicSharedMemorySize, SMEMG);
        cudaFuncSetAttribute(mma_gemm<2,0,4*Cc,Cc>, cudaFuncAttributeMaxDynamicSharedMemorySize, SMEMG);
        cudaFuncSetAttribute(mma_conv<1,Cc,64>,     cudaFuncAttributeMaxDynamicSharedMemorySize, SMEMG);
        cudaFuncSetAttribute(mma_conv<0,64,Cc>,     cudaFuncAttributeMaxDynamicSharedMemorySize, SMEMG);
        attr_set = true;
    }

    f2b_all<<<(STOT + 255)/256, 256>>>(qkv_w, proj_w, fc1w, fc2w, c1w, c2w,
                                       wqkv, wproj, wfc1, wfc2, wc1, wc2);
    btb_kernel<<<NHc*Nc*Nc/256, 256>>>(rpb, rpi, btb);

    ln_kernel<<<NPIX/8, 256>>>(x, n1w, n1b, xnb);
    // conv branch
    mma_conv<1, Cc, 64><<<dim3(Bc*Hc, 1), 256, SMEMG>>>(xnb, wc1, c1b, cv1b);
    mma_conv<0, 64, Cc><<<dim3(Bc*Hc, 3), 256, SMEMG>>>(cv1b, wc2, c2b, cv2b);
    pool_kernel<<<Bc*64, Cc>>>(cv2b, pp);
    ca_kernel<<<1, 256>>>(pp, ca1w, ca1b, ca2w, ca2b, cab);
    // attention branch
    mma_gemm<0, 1, Cc, 3*Cc><<<dim3(NPIX/128, 9), 256, SMEMG>>>(xnb, wqkv, qkv_b, qkvb,
                                                         nullptr, nullptr, nullptr, nullptr);
    attn_mma<<<dim3(256, NHc), 256, 3*256*QP*sizeof(bf16)>>>(qkvb, btb, atb);
    mma_gemm<3, 0, Cc, Cc><<<dim3(NPIX/128, 3), 256, SMEMG>>>(atb, wproj, proj_b, y,
                                                       nullptr, x, cv2b, cab);
    // MLP
    ln_kernel<<<NPIX/8, 256>>>(y, n2w, n2b, ynb);
    mma_gemm<1, 0, Cc, 4*Cc><<<dim3(NPIX/128, 12), 256, SMEMG>>>(ynb, wfc1, fc1b, hb,
                                                          nullptr, nullptr, nullptr, nullptr);
    mma_gemm<2, 0, 4*Cc, Cc><<<dim3(NPIX/128, 3), 256, SMEMG>>>(hb, wfc2, fc2b, out,
                                                         y, nullptr, nullptr, nullptr);
}

// round 12
// speedup vs baseline: 1.1798x; 1.1798x over previous
#include <cuda_runtime.h>
#include <cuda_bf16.h>
#include <math.h>
#include <stdint.h>

typedef __nv_bfloat16 bf16;

#define Bc 4
#define Hc 128
#define Wc 128
#define Cc 192
#define NHc 6
#define WSc 16
#define SSc 8
#define Nc 256
#define HDc 32
#define NPIX (Bc*Hc*Wc)            // 65536
#define ATT_SCALE 0.17677669529663687f

#define AP 40       // A smem row stride (bf16 elems)
#define BP2 72      // B smem row stride
#define QP 40       // attention smem row stride

// ---------------- scratch (device globals) -----------------------------------
__device__ bf16  g_xnb [NPIX*Cc];
__device__ bf16  g_qkvb[(size_t)NPIX*3*Cc];
__device__ bf16  g_atb [NPIX*Cc];
__device__ bf16  g_cv1b[NPIX*64];
__device__ bf16  g_cv2b[NPIX*Cc];
__device__ float g_y   [NPIX*Cc];
__device__ bf16  g_ynb [NPIX*Cc];
__device__ bf16  g_hb  [(size_t)NPIX*4*Cc];
__device__ float g_pp  [Bc*64*Cc];
__device__ float g_ca  [Bc*Cc];
__device__ bf16  g_btb [NHc*Nc*Nc];
__device__ bf16  g_wqkv [Cc*3*Cc];
__device__ bf16  g_wproj[Cc*Cc];
__device__ bf16  g_wfc1 [Cc*4*Cc];
__device__ bf16  g_wfc2 [4*Cc*Cc];
__device__ bf16  g_wc1  [9*Cc*64];
__device__ bf16  g_wc2  [9*64*Cc];

__device__ __forceinline__ float gelu_exact(float x) {
    return 0.5f * x * (1.f + erff(x * 0.70710678118654752f));
}

// ---------------- ptx helpers ------------------------------------------------
#define CP16(dst, src) asm volatile("cp.async.cg.shared.global [%0], [%1], 16;\n" :: "r"(dst), "l"(src))
#define CP16Z(dst, src, sz) asm volatile("cp.async.cg.shared.global [%0], [%1], 16, %2;\n" :: "r"(dst), "l"(src), "r"(sz))
#define CP_COMMIT asm volatile("cp.async.commit_group;\n")
#define CP_WAITG1 asm volatile("cp.async.wait_group 1;\n")

__device__ __forceinline__ void ldsm4(uint32_t* r, uint32_t a) {
    asm volatile("ldmatrix.sync.aligned.m8n8.x4.shared.b16 {%0,%1,%2,%3},[%4];"
        : "=r"(r[0]), "=r"(r[1]), "=r"(r[2]), "=r"(r[3]) : "r"(a));
}
__device__ __forceinline__ void ldsm4t(uint32_t* r, uint32_t a) {
    asm volatile("ldmatrix.sync.aligned.m8n8.x4.trans.shared.b16 {%0,%1,%2,%3},[%4];"
        : "=r"(r[0]), "=r"(r[1]), "=r"(r[2]), "=r"(r[3]) : "r"(a));
}
__device__ __forceinline__ void mma_bf16(float* c, const uint32_t* a, const uint32_t* b) {
    asm volatile(
        "mma.sync.aligned.m16n8k16.row.col.f32.bf16.bf16.f32 "
        "{%0,%1,%2,%3}, {%4,%5,%6,%7}, {%8,%9}, {%0,%1,%2,%3};\n"
        : "+f"(c[0]), "+f"(c[1]), "+f"(c[2]), "+f"(c[3])
        : "r"(a[0]), "r"(a[1]), "r"(a[2]), "r"(a[3]), "r"(b[0]), "r"(b[1]));
}
__device__ __forceinline__ uint32_t pkbf2(float a, float b) {
    __nv_bfloat162 t = __floats2bfloat162_rn(a, b);
    return *(uint32_t*)&t;
}

// ---------------- batched weight convert --------------------------------------
#define S0 110592
#define S1 36864
#define S2 147456
#define S3 147456
#define S4 110592
#define S5 110592
#define STOT (S0+S1+S2+S3+S4+S5)
__global__ void f2b_all(const float* __restrict__ a0, const float* __restrict__ a1,
                        const float* __restrict__ a2, const float* __restrict__ a3,
                        const float* __restrict__ a4, const float* __restrict__ a5,
                        bf16* o0, bf16* o1, bf16* o2, bf16* o3, bf16* o4, bf16* o5) {
    int i = blockIdx.x * 256 + threadIdx.x;
    if (i >= STOT) return;
    if (i < S0)                { o0[i] = __float2bfloat16(a0[i]); return; }
    i -= S0;
    if (i < S1)                { o1[i] = __float2bfloat16(a1[i]); return; }
    i -= S1;
    if (i < S2)                { o2[i] = __float2bfloat16(a2[i]); return; }
    i -= S2;
    if (i < S3)                { o3[i] = __float2bfloat16(a3[i]); return; }
    i -= S3;
    if (i < S4)                { o4[i] = __float2bfloat16(a4[i]); return; }
    i -= S4;
    o5[i] = __float2bfloat16(a5[i]);
}

__global__ void btb_kernel(const float* __restrict__ rpb, const int* __restrict__ rpi,
                           bf16* __restrict__ btb) {
    int idx = blockIdx.x * 256 + threadIdx.x;
    int h = idx >> 16;
    int qk = idx & 65535;
    btb[idx] = __float2bfloat16(rpb[rpi[qk]*NHc + h]);
}

// ---------------- LayerNorm: warp per token ----------------------------------
__global__ __launch_bounds__(256) void ln_kernel(
        const float* __restrict__ x, const float* __restrict__ g,
        const float* __restrict__ b, bf16* __restrict__ out) {
    int t = (blockIdx.x * 256 + threadIdx.x) >> 5;
    int lane = threadIdx.x & 31;
    const float* row = x + (size_t)t * Cc;
    float v[6], s = 0.f, ss = 0.f;
    #pragma unroll
    for (int i = 0; i < 6; i++) {
        v[i] = row[i*32 + lane];
        s += v[i]; ss += v[i]*v[i];
    }
    #pragma unroll
    for (int o = 16; o; o >>= 1) {
        s  += __shfl_xor_sync(0xffffffffu, s, o);
        ss += __shfl_xor_sync(0xffffffffu, ss, o);
    }
    float m = s * (1.f/Cc);
    float inv = rsqrtf(ss * (1.f/Cc) - m*m + 1e-5f);
    #pragma unroll
    for (int i = 0; i < 6; i++) {
        int c = i*32 + lane;
        out[(size_t)t*Cc + c] = __float2bfloat16((v[i] - m)*inv*g[c] + b[c]);
    }
}

// ---------------- MMA compute on one staged chunk (precomputed offsets) ------
__device__ __forceinline__ void mma_stage(uint32_t ab, uint32_t bb,
        const uint32_t aoff[2][2], const uint32_t boff[2][2], float acc[2][4][4]) {
    #pragma unroll
    for (int kk = 0; kk < 2; kk++) {
        uint32_t af[2][4], bq[2][4];
        ldsm4(af[0], ab + aoff[0][kk]);
        ldsm4(af[1], ab + aoff[1][kk]);
        ldsm4t(bq[0], bb + boff[kk][0]);
        ldsm4t(bq[1], bb + boff[kk][1]);
        #pragma unroll
        for (int mi = 0; mi < 2; mi++) {
            mma_bf16(acc[mi][0], af[mi], &bq[0][0]);
            mma_bf16(acc[mi][1], af[mi], &bq[0][2]);
            mma_bf16(acc[mi][2], af[mi], &bq[1][0]);
            mma_bf16(acc[mi][3], af[mi], &bq[1][2]);
        }
    }
}

// precompute ldsm byte-offsets (relative to stage base)
__device__ __forceinline__ void mk_mma_offs(int wm, int wn, int lane,
        uint32_t aoff[2][2], uint32_t boff[2][2]) {
    #pragma unroll
    for (int mi = 0; mi < 2; mi++)
        #pragma unroll
        for (int kk = 0; kk < 2; kk++) {
            int r = wm*32 + mi*16 + (lane & 15);
            int ko = kk*16 + ((lane >> 4) << 3);
            aoff[mi][kk] = (uint32_t)((r*AP + ko) * 2);
        }
    #pragma unroll
    for (int kk = 0; kk < 2; kk++)
        #pragma unroll
        for (int nh = 0; nh < 2; nh++) {
            int krow = kk*16 + (lane & 7) + (lane & 8);
            int ncol = wn*32 + nh*16 + ((lane >> 4) << 3);
            boff[kk][nh] = (uint32_t)((krow*BP2 + ncol) * 2);
        }
}

// ---------------- GEMM: MODE 0 bf16; 1 gelu bf16; 2 fp32+res; 3 proj-combine -
template<int MODE, int GATHER, int K, int N>
__global__ __launch_bounds__(256, 3) void mma_gemm(
        const bf16* __restrict__ A, const bf16* __restrict__ W,
        const float* __restrict__ bias, void* __restrict__ Cout_,
        const float* __restrict__ Rres, const float* __restrict__ xres,
        const bf16* __restrict__ cv2b, const float* __restrict__ cab) {
    __shared__ __align__(16) bf16 As[3][128*AP];
    __shared__ __align__(16) bf16 Bs[3][32*BP2];
    constexpr int nk = K >> 5;
    constexpr uint32_t AS_ST = 128*AP*2;
    constexpr uint32_t BS_ST = 32*BP2*2;
    int tid = threadIdx.x;
    int m0 = blockIdx.x * 128, n0 = blockIdx.y * 64;
    int warp = tid >> 5, lane = tid & 31;
    int wm = warp & 3, wn = warp >> 2;
    int g = lane >> 2, tg = lane & 3;

    // hoisted A-load addressing: rows rb, rb+64 ; chunk-local col group kc*8 (0..24)
    int rb = tid >> 2, kc = tid & 3;
    const bf16* srcA[2];
    uint32_t dofA[2];
    #pragma unroll
    for (int i = 0; i < 2; i++) {
        int r = rb + i*64;
        int row;
        if (GATHER) {
            int t = m0 + r; int n = t & 255, win = t >> 8;
            int b = win >> 6, wl = win & 63;
            int hh = (((wl >> 3) << 4) + (n >> 4) + SSc) & 127;
            int ww = (((wl & 7) << 4) + (n & 15) + SSc) & 127;
            row = (b*Hc + hh)*Wc + ww;
        } else row = m0 + r;
        srcA[i] = A + (size_t)row*K + kc*8;
        dofA[i] = (uint32_t)((r*AP + kc*8) * 2);
    }
    // B-load: 32 k-rows x 8 col-groups, 1 load per thread
    int rbB = tid >> 3, kcB = tid & 7;
    const bf16* srcB = W + (size_t)rbB*N + n0 + kcB*8;
    uint32_t dofB = (uint32_t)((rbB*BP2 + kcB*8) * 2);

    uint32_t asb = (uint32_t)__cvta_generic_to_shared(&As[0][0]);
    uint32_t bsb = (uint32_t)__cvta_generic_to_shared(&Bs[0][0]);
    uint32_t aoff[2][2], boff[2][2];
    mk_mma_offs(wm, wn, lane, aoff, boff);

    float acc[2][4][4];
    #pragma unroll
    for (int a = 0; a < 2; a++)
        #pragma unroll
        for (int b = 0; b < 4; b++)
            #pragma unroll
            for (int c = 0; c < 4; c++) acc[a][b][c] = 0.f;

    auto loadAB = [&](int st, int k0) {
        uint32_t ab = asb + st*AS_ST, bb = bsb + st*BS_ST;
        CP16(ab + dofA[0], srcA[0] + k0);
        CP16(ab + dofA[1], srcA[1] + k0);
        CP16(bb + dofB, srcB + (size_t)k0*N);
    };

    loadAB(0, 0); CP_COMMIT;
    if (nk > 1) loadAB(1, 32);
    CP_COMMIT;

    int sl = 0;
    for (int c = 0; c < nk; c++) {
        CP_WAITG1;
        __syncthreads();
        int nx = c + 2;
        int sn = sl + 2; if (sn >= 3) sn -= 3;
        if (nx < nk) loadAB(sn, nx*32);
        CP_COMMIT;
        mma_stage(asb + sl*AS_ST, bsb + sl*BS_ST, aoff, boff, acc);
        if (++sl == 3) sl = 0;
    }

    #pragma unroll
    for (int mi = 0; mi < 2; mi++) {
        #pragma unroll
        for (int nj = 0; nj < 4; nj++) {
            int r1 = m0 + wm*32 + mi*16 + g;
            int r2 = r1 + 8;
            int cg = n0 + wn*32 + nj*8 + tg*2;
            float b0 = bias[cg], b1 = bias[cg+1];
            float v00 = acc[mi][nj][0] + b0, v01 = acc[mi][nj][1] + b1;
            float v10 = acc[mi][nj][2] + b0, v11 = acc[mi][nj][3] + b1;
            if (MODE == 0) {
                bf16* C = (bf16*)Cout_;
                *(__nv_bfloat162*)(C + (size_t)r1*N + cg) = __floats2bfloat162_rn(v00, v01);
                *(__nv_bfloat162*)(C + (size_t)r2*N + cg) = __floats2bfloat162_rn(v10, v11);
            } else if (MODE == 1) {
                bf16* C = (bf16*)Cout_;
                *(__nv_bfloat162*)(C + (size_t)r1*N + cg) =
                    __floats2bfloat162_rn(gelu_exact(v00), gelu_exact(v01));
                *(__nv_bfloat162*)(C + (size_t)r2*N + cg) =
                    __floats2bfloat162_rn(gelu_exact(v10), gelu_exact(v11));
            } else if (MODE == 2) {
                float* C = (float*)Cout_;
                float2 ra = *(const float2*)(Rres + (size_t)r1*N + cg);
                float2 rb2 = *(const float2*)(Rres + (size_t)r2*N + cg);
                *(float2*)(C + (size_t)r1*N + cg) = make_float2(v00+ra.x, v01+ra.y);
                *(float2*)(C + (size_t)r2*N + cg) = make_float2(v10+rb2.x, v11+rb2.y);
            } else {
                float* Y = (float*)Cout_;
                int rr[2] = {r1, r2};
                float vv[2][2] = {{v00, v01}, {v10, v11}};
                #pragma unroll
                for (int q = 0; q < 2; q++) {
                    int t = rr[q];
                    int n = t & 255, win = t >> 8;
                    int b = win >> 6, wl = win & 63;
                    int hh = ((wl >> 3) << 4) + (n >> 4);
                    int ww = ((wl & 7) << 4) + (n & 15);
                    int oh = (hh + SSc) & 127, ow = (ww + SSc) & 127;
                    size_t p = (size_t)((b*Hc + oh)*Wc + ow);
                    float2 xv = *(const float2*)(xres + p*Cc + cg);
                    float2 cav = *(const float2*)(cab + b*Cc + cg);
                    float2 cvv = __bfloat1622float2(*(const __nv_bfloat162*)(cv2b + p*Cc + cg));
                    *(float2*)(Y + p*Cc + cg) = make_float2(
                        xv.x + vv[q][0] + cvv.x*cav.x*0.01f,
                        xv.y + vv[q][1] + cvv.y*cav.y*0.01f);
                }
            }
        }
    }
}

// ---------------- 3x3 conv (implicit GEMM, hoisted addressing) ----------------
template<int MODE, int Cin, int Cout>
__global__ __launch_bounds__(256, 3) void mma_conv(
        const bf16* __restrict__ X, const bf16* __restrict__ Wt,
        const float* __restrict__ bias, bf16* __restrict__ Y) {
    __shared__ __align__(16) bf16 As[3][128*AP];
    __shared__ __align__(16) bf16 Bs[3][32*BP2];
    constexpr int CCH = Cin >> 5;
    constexpr int nk = 9 * CCH;
    constexpr uint32_t AS_ST = 128*AP*2;
    constexpr uint32_t BS_ST = 32*BP2*2;
    int bi = blockIdx.x;
    int b = bi >> 7, h = bi & 127;
    int n0 = blockIdx.y * 64;
    int tid = threadIdx.x;
    int warp = tid >> 5, lane = tid & 31;
    int wm = warp & 3, wn = warp >> 2;
    int g = lane >> 2, tg = lane & 3;

    // A-load: 2 rows per thread (rb2, rb2+64), kc4 = chunk-local 8-elem group
    int rb2 = tid >> 2, kc4 = tid & 3;
    uint32_t dofA[2];
    dofA[0] = (uint32_t)((rb2*AP + kc4*8) * 2);
    dofA[1] = (uint32_t)(((rb2+64)*AP + kc4*8) * 2);
    // per-dh row bases (clamped) + ok flags
    const bf16* rowbase[3];
    bool okH[3];
    #pragma unroll
    for (int d = 0; d < 3; d++) {
        int ih = h + d - 1;
        okH[d] = (ih >= 0 && ih < Hc);
        int ihc = min(max(ih, 0), Hc-1);
        rowbase[d] = X + (size_t)((b*Hc + ihc)*Wc) * Cin + kc4*8;
    }
    // per-dw column offsets + ok flags for this thread's 2 rows
    int iwc[3][2]; bool okW[3][2];
    #pragma unroll
    for (int d = 0; d < 3; d++)
        #pragma unroll
        for (int i = 0; i < 2; i++) {
            int r = rb2 + i*64;
            int iw = r + d - 1;
            okW[d][i] = (iw >= 0 && iw < Wc);
            iwc[d][i] = min(max(iw, 0), Wc-1);
        }
    // B: linear in global k = chunk*32 + kb
    const bf16* srcB = Wt + (size_t)(tid >> 3)*Cout + n0 + (tid & 7)*8;
    uint32_t dofB = (uint32_t)(((tid >> 3)*BP2 + (tid & 7)*8) * 2);

    uint32_t asb = (uint32_t)__cvta_generic_to_shared(&As[0][0]);
    uint32_t bsb = (uint32_t)__cvta_generic_to_shared(&Bs[0][0]);
    uint32_t aoff[2][2], boff[2][2];
    mk_mma_offs(wm, wn, lane, aoff, boff);

    float acc[2][4][4];
    #pragma unroll
    for (int a = 0; a < 2; a++)
        #pragma unroll
        for (int bb = 0; bb < 4; bb++)
            #pragma unroll
            for (int c = 0; c < 4; c++) acc[a][bb][c] = 0.f;

    auto loadAB = [&](int st, int chunk) {
        int tap = chunk / CCH;           // compile-time divisor
        int ci0 = (chunk - tap*CCH) * 32;
        int dh = tap/3, dw = tap - dh*3; // 0..2 each
        uint32_t ab = asb + st*AS_ST, bb = bsb + st*BS_ST;
        const bf16* rbp = rowbase[dh] + ci0;
        #pragma unroll
        for (int i = 0; i < 2; i++) {
            int sz = (okH[dh] && okW[dw][i]) ? 16 : 0;
            CP16Z(ab + dofA[i], rbp + (size_t)iwc[dw][i]*Cin, sz);
        }
        CP16(bb + dofB, srcB + (size_t)chunk*32*Cout);
    };

    loadAB(0, 0); CP_COMMIT;
    loadAB(1, 1); CP_COMMIT;

    int sl = 0;
    for (int c = 0; c < nk; c++) {
        CP_WAITG1;
        __syncthreads();
        int nx = c + 2;
        int sn = sl + 2; if (sn >= 3) sn -= 3;
        if (nx < nk) loadAB(sn, nx);
        CP_COMMIT;
        mma_stage(asb + sl*AS_ST, bsb + sl*BS_ST, aoff, boff, acc);
        if (++sl == 3) sl = 0;
    }

    #pragma unroll
    for (int mi = 0; mi < 2; mi++) {
        #pragma unroll
        for (int nj = 0; nj < 4; nj++) {
            int p1 = (b*Hc + h)*Wc + wm*32 + mi*16 + g;
            int p2 = p1 + 8;
            int cg = n0 + wn*32 + nj*8 + tg*2;
            float b0 = bias[cg], b1 = bias[cg+1];
            float v00 = acc[mi][nj][0] + b0, v01 = acc[mi][nj][1] + b1;
            float v10 = acc[mi][nj][2] + b0, v11 = acc[mi][nj][3] + b1;
            if (MODE == 1) {
                v00 = gelu_exact(v00); v01 = gelu_exact(v01);
                v10 = gelu_exact(v10); v11 = gelu_exact(v11);
            }
            *(__nv_bfloat162*)(Y + (size_t)p1*Cout + cg) = __floats2bfloat162_rn(v00, v01);
            *(__nv_bfloat162*)(Y + (size_t)p2*Cout + cg) = __floats2bfloat162_rn(v10, v11);
        }
    }
}

// ---------------- pool + channel attention -----------------------------------
__global__ void pool_kernel(const bf16* __restrict__ cv2b, float* __restrict__ pp) {
    int blk = blockIdx.x;
    int b = blk >> 6, chunk = blk & 63;
    int c = threadIdx.x;
    float s = 0.f;
    int base = b*16384 + chunk*256;
    for (int p = 0; p < 256; p++) s += __bfloat162float(cv2b[(size_t)(base + p)*Cc + c]);
    pp[blk*Cc + c] = s;
}

__global__ void ca_kernel(const float* __restrict__ pp,
                          const float* __restrict__ w1, const float* __restrict__ b1,
                          const float* __restrict__ w2, const float* __restrict__ b2,
                          float* __restrict__ ca) {
    __shared__ float pooled[Bc*Cc];
    __shared__ float t1[Bc*6];
    int tid = threadIdx.x;
    for (int i = tid; i < Bc*Cc; i += 256) {
        int b = i / Cc, c = i % Cc;
        float s = 0.f;
        for (int j = 0; j < 64; j++) s += pp[(b*64 + j)*Cc + c];
        pooled[i] = s * (1.f/16384.f);
    }
    __syncthreads();
    if (tid < Bc*6) {
        int b = tid / 6, j = tid % 6;
        float s = b1[j];
        for (int c = 0; c < Cc; c++) s += pooled[b*Cc + c] * w1[c*6 + j];
        t1[tid] = fmaxf(s, 0.f);
    }
    __syncthreads();
    for (int i = tid; i < Bc*Cc; i += 256) {
        int b = i / Cc, c = i % Cc;
        float s = b2[c];
        #pragma unroll
        for (int j = 0; j < 6; j++) s += t1[b*6 + j] * w2[j*Cc + c];
        ca[i] = 1.f / (1.f + expf(-s));
    }
}

// ---------------- flash window attention via tensor-core MMA ------------------
__global__ __launch_bounds__(256) void attn_mma(
        const bf16* __restrict__ qkvb, const bf16* __restrict__ btb,
        bf16* __restrict__ out) {
    extern __shared__ __align__(16) bf16 smA[];
    bf16* Qs = smA;
    bf16* Ks = smA + 256*QP;
    bf16* Vs = smA + 2*256*QP;
    int win = blockIdx.x, h = blockIdx.y;
    int tid = threadIdx.x;
    int warp = tid >> 5, lane = tid & 31;
    int g = lane >> 2, tg = lane & 3;
    int m0 = warp * 32;

    {
        const uint4* src = (const uint4*)(qkvb + (size_t)(win*Nc + tid)*576 + h*HDc);
        uint4* qd = (uint4*)(Qs + tid*QP);
        uint4* kd = (uint4*)(Ks + tid*QP);
        uint4* vd = (uint4*)(Vs + tid*QP);
        #pragma unroll
        for (int i = 0; i < 4; i++) {
            qd[i] = src[i];
            kd[i] = src[i + 24];
            vd[i] = src[i + 48];
        }
    }
    __syncthreads();

    uint32_t qf[2][2][4];
    #pragma unroll
    for (int mi = 0; mi < 2; mi++)
        #pragma unroll
        for (int ks = 0; ks < 2; ks++) {
            int r = m0 + mi*16 + (lane & 15);
            int kofs = ks*16 + ((lane >> 4) << 3);
            ldsm4(qf[mi][ks], (uint32_t)__cvta_generic_to_shared(Qs + r*QP + kofs));
        }

    const bf16* cb = btb + ((size_t)h << 16);

    int wl = win & 63;
    bool er = (wl >> 3) == 7, ec = (wl & 7) == 7;
    bool edge = er || ec;
    int lq[2][2];
    #pragma unroll
    for (int mi = 0; mi < 2; mi++)
        #pragma unroll
        for (int rh = 0; rh < 2; rh++) {
            int q = m0 + mi*16 + g + rh*8;
            int rc = er ? (((q >> 4) < 8) ? 1 : 2) : 0;
            int cc = ec ? (((q & 15) < 8) ? 1 : 2) : 0;
            lq[mi][rh] = rc*3 + cc;
        }

    float mx[2][2], lsum[2][2];
    float o[2][4][4];
    #pragma unroll
    for (int mi = 0; mi < 2; mi++)
        #pragma unroll
        for (int rh = 0; rh < 2; rh++) { mx[mi][rh] = -1e30f; lsum[mi][rh] = 0.f; }
    #pragma unroll
    for (int mi = 0; mi < 2; mi++)
        #pragma unroll
        for (int nt = 0; nt < 4; nt++)
            #pragma unroll
            for (int e = 0; e < 4; e++) o[mi][nt][e] = 0.f;

    for (int c0 = 0; c0 < Nc; c0 += 32) {
        float s[2][4][4];
        #pragma unroll
        for (int mi = 0; mi < 2; mi++)
            #pragma unroll
            for (int nj = 0; nj < 4; nj++)
                #pragma unroll
                for (int e = 0; e < 4; e++) s[mi][nj][e] = 0.f;

        #pragma unroll
        for (int ks = 0; ks < 2; ks++) {
            uint32_t kf[2][4];
            #pragma unroll
            for (int np = 0; np < 2; np++) {
                int n = c0 + np*16 + (lane & 7) + ((lane >> 4) << 3);
                int kc = ks*16 + ((lane >> 3) & 1)*8;
                ldsm4(kf[np], (uint32_t)__cvta_generic_to_shared(Ks + n*QP + kc));
            }
            #pragma unroll
            for (int mi = 0; mi < 2; mi++) {
                mma_bf16(s[mi][0], qf[mi][ks], &kf[0][0]);
                mma_bf16(s[mi][1], qf[mi][ks], &kf[0][2]);
                mma_bf16(s[mi][2], qf[mi][ks], &kf[1][0]);
                mma_bf16(s[mi][3], qf[mi][ks], &kf[1][2]);
            }
        }

        int lk[4][2];
        if (edge) {
            #pragma unroll
            for (int nj = 0; nj < 4; nj++)
                #pragma unroll
                for (int e = 0; e < 2; e++) {
                    int kcol = c0 + nj*8 + tg*2 + e;
                    int rc = er ? (((kcol >> 4) < 8) ? 1 : 2) : 0;
                    int cc = ec ? (((kcol & 15) < 8) ? 1 : 2) : 0;
                    lk[nj][e] = rc*3 + cc;
                }
        }
        #pragma unroll
        for (int mi = 0; mi < 2; mi++) {
            int row0 = m0 + mi*16 + g;
            #pragma unroll
            for (int nj = 0; nj < 4; nj++) {
                int col = c0 + nj*8 + tg*2;
                float2 b0 = __bfloat1622float2(*(const __nv_bfloat162*)(cb + (size_t)row0*Nc + col));
                float2 b1 = __bfloat1622float2(*(const __nv_bfloat162*)(cb + (size_t)(row0+8)*Nc + col));
                s[mi][nj][0] = s[mi][nj][0]*ATT_SCALE + b0.x;
                s[mi][nj][1] = s[mi][nj][1]*ATT_SCALE + b0.y;
                s[mi][nj][2] = s[mi][nj][2]*ATT_SCALE + b1.x;
                s[mi][nj][3] = s[mi][nj][3]*ATT_SCALE + b1.y;
                if (edge) {
                    s[mi][nj][0] += (lq[mi][0] == lk[nj][0]) ? 0.f : -100.f;
                    s[mi][nj][1] += (lq[mi][0] == lk[nj][1]) ? 0.f : -100.f;
                    s[mi][nj][2] += (lq[mi][1] == lk[nj][0]) ? 0.f : -100.f;
                    s[mi][nj][3] += (lq[mi][1] == lk[nj][1]) ? 0.f : -100.f;
                }
            }
            #pragma unroll
            for (int rh = 0; rh < 2; rh++) {
                int e0 = rh*2;
                float m_ = fmaxf(fmaxf(s[mi][0][e0], s[mi][0][e0+1]),
                                 fmaxf(s[mi][1][e0], s[mi][1][e0+1]));
                m_ = fmaxf(m_, fmaxf(fmaxf(s[mi][2][e0], s[mi][2][e0+1]),
                                     fmaxf(s[mi][3][e0], s[mi][3][e0+1])));
                m_ = fmaxf(m_, __shfl_xor_sync(0xffffffffu, m_, 1));
                m_ = fmaxf(m_, __shfl_xor_sync(0xffffffffu, m_, 2));
                float newm = fmaxf(mx[mi][rh], m_);
                float sc = __expf(mx[mi][rh] - newm);
                mx[mi][rh] = newm;
                float ps = 0.f;
                #pragma unroll
                for (int nj = 0; nj < 4; nj++) {
                    float p0 = __expf(s[mi][nj][e0]   - newm);
                    float p1 = __expf(s[mi][nj][e0+1] - newm);
                    s[mi][nj][e0] = p0; s[mi][nj][e0+1] = p1;
                    ps += p0 + p1;
                }
                ps += __shfl_xor_sync(0xffffffffu, ps, 1);
                ps += __shfl_xor_sync(0xffffffffu, ps, 2);
                lsum[mi][rh] = lsum[mi][rh]*sc + ps;
                #pragma unroll
                for (int nt = 0; nt < 4; nt++) {
                    o[mi][nt][e0]   *= sc;
                    o[mi][nt][e0+1] *= sc;
                }
            }
        }

        #pragma unroll
        for (int ks2 = 0; ks2 < 2; ks2++) {
            uint32_t vf[2][4];
            int krow = c0 + ks2*16 + (lane & 7) + (lane & 8);
            #pragma unroll
            for (int dp = 0; dp < 2; dp++)
                ldsm4t(vf[dp], (uint32_t)__cvta_generic_to_shared(
                    Vs + krow*QP + dp*16 + ((lane >> 4) << 3)));
            #pragma unroll
            for (int mi = 0; mi < 2; mi++) {
                uint32_t af[4];
                af[0] = pkbf2(s[mi][2*ks2][0],   s[mi][2*ks2][1]);
                af[1] = pkbf2(s[mi][2*ks2][2],   s[mi][2*ks2][3]);
                af[2] = pkbf2(s[mi][2*ks2+1][0], s[mi][2*ks2+1][1]);
                af[3] = pkbf2(s[mi][2*ks2+1][2], s[mi][2*ks2+1][3]);
                mma_bf16(o[mi][0], af, &vf[0][0]);
                mma_bf16(o[mi][1], af, &vf[0][2]);
                mma_bf16(o[mi][2], af, &vf[1][0]);
                mma_bf16(o[mi][3], af, &vf[1][2]);
            }
        }
    }

    #pragma unroll
    for (int mi = 0; mi < 2; mi++) {
        #pragma unroll
        for (int rh = 0; rh < 2; rh++) {
            float inv = 1.f / lsum[mi][rh];
            int row = win*Nc + m0 + mi*16 + g + rh*8;
            bf16* orow = out + (size_t)row*Cc + h*HDc;
            #pragma unroll
            for (int nt = 0; nt < 4; nt++) {
                *(__nv_bfloat162*)(orow + nt*8 + tg*2) =
                    __floats2bfloat162_rn(o[mi][nt][rh*2]*inv, o[mi][nt][rh*2+1]*inv);
            }
        }
    }
}

// ---------------- launch -----------------------------------------------------
extern "C" void kernel_launch(void* const* d_in, const int* in_sizes, int n_in,
                              void* d_out, int out_size) {
    const float* x     = (const float*)d_in[0];
    const float* qkv_w = (const float*)d_in[1];
    const float* qkv_b = (const float*)d_in[2];
    const float* proj_w= (const float*)d_in[3];
    const float* proj_b= (const float*)d_in[4];
    const float* rpb   = (const float*)d_in[5];
    const float* n1w   = (const float*)d_in[6];
    const float* n1b   = (const float*)d_in[7];
    const float* n2w   = (const float*)d_in[8];
    const float* n2b   = (const float*)d_in[9];
    const float* c1w   = (const float*)d_in[10];
    const float* c1b   = (const float*)d_in[11];
    const float* c2w   = (const float*)d_in[12];
    const float* c2b   = (const float*)d_in[13];
    const float* ca1w  = (const float*)d_in[14];
    const float* ca1b  = (const float*)d_in[15];
    const float* ca2w  = (const float*)d_in[16];
    const float* ca2b  = (const float*)d_in[17];
    const float* fc1w  = (const float*)d_in[18];
    const float* fc1b  = (const float*)d_in[19];
    const float* fc2w  = (const float*)d_in[20];
    const float* fc2b  = (const float*)d_in[21];
    const int*   rpi   = (const int*)d_in[22];
    float* out = (float*)d_out;

    bf16 *xnb, *qkvb, *atb, *cv1b, *cv2b, *ynb, *hb, *btb;
    bf16 *wqkv, *wproj, *wfc1, *wfc2, *wc1, *wc2;
    float *y, *pp, *cab;
    cudaGetSymbolAddress((void**)&xnb,  g_xnb);
    cudaGetSymbolAddress((void**)&qkvb, g_qkvb);
    cudaGetSymbolAddress((void**)&atb,  g_atb);
    cudaGetSymbolAddress((void**)&cv1b, g_cv1b);
    cudaGetSymbolAddress((void**)&cv2b, g_cv2b);
    cudaGetSymbolAddress((void**)&y,    g_y);
    cudaGetSymbolAddress((void**)&ynb,  g_ynb);
    cudaGetSymbolAddress((void**)&hb,   g_hb);
    cudaGetSymbolAddress((void**)&pp,   g_pp);
    cudaGetSymbolAddress((void**)&cab,  g_ca);
    cudaGetSymbolAddress((void**)&btb,  g_btb);
    cudaGetSymbolAddress((void**)&wqkv, g_wqkv);
    cudaGetSymbolAddress((void**)&wproj,g_wproj);
    cudaGetSymbolAddress((void**)&wfc1, g_wfc1);
    cudaGetSymbolAddress((void**)&wfc2, g_wfc2);
    cudaGetSymbolAddress((void**)&wc1,  g_wc1);
    cudaGetSymbolAddress((void**)&wc2,  g_wc2);

    static bool attr_set = false;
    if (!attr_set) {
        cudaFuncSetAttribute(attn_mma, cudaFuncAttributeMaxDynamicSharedMemorySize,
                             3*256*QP*sizeof(bf16));
        attr_set = true;
    }

    f2b_all<<<(STOT + 255)/256, 256>>>(qkv_w, proj_w, fc1w, fc2w, c1w, c2w,
                                       wqkv, wproj, wfc1, wfc2, wc1, wc2);
    btb_kernel<<<NHc*Nc*Nc/256, 256>>>(rpb, rpi, btb);

    ln_kernel<<<NPIX/8, 256>>>(x, n1w, n1b, xnb);
    // conv branch
    mma_conv<1, Cc, 64><<<dim3(Bc*Hc, 1), 256>>>(xnb, wc1, c1b, cv1b);
    mma_conv<0, 64, Cc><<<dim3(Bc*Hc, 3), 256>>>(cv1b, wc2, c2b, cv2b);
    pool_kernel<<<Bc*64, Cc>>>(cv2b, pp);
    ca_kernel<<<1, 256>>>(pp, ca1w, ca1b, ca2w, ca2b, cab);
    // attention branch
    mma_gemm<0, 1, Cc, 3*Cc><<<dim3(NPIX/128, 9), 256>>>(xnb, wqkv, qkv_b, qkvb,
                                                         nullptr, nullptr, nullptr, nullptr);
    attn_mma<<<dim3(256, NHc), 256, 3*256*QP*sizeof(bf16)>>>(qkvb, btb, atb);
    mma_gemm<3, 0, Cc, Cc><<<dim3(NPIX/128, 3), 256>>>(atb, wproj, proj_b, y,
                                                       nullptr, x, cv2b, cab);
    // MLP
    ln_kernel<<<NPIX/8, 256>>>(y, n2w, n2b, ynb);
    mma_gemm<1, 0, Cc, 4*Cc><<<dim3(NPIX/128, 12), 256>>>(ynb, wfc1, fc1b, hb,
                                                          nullptr, nullptr, nullptr, nullptr);
    mma_gemm<2, 0, 4*Cc, Cc><<<dim3(NPIX/128, 3), 256>>>(hb, wfc2, fc2b, out,
                                                         y, nullptr, nullptr, nullptr);
}

// round 13
// speedup vs baseline: 1.2303x; 1.0428x over previous
#include <cuda_runtime.h>
#include <cuda_bf16.h>
#include <math.h>
#include <stdint.h>

typedef __nv_bfloat16 bf16;

#define Bc 4
#define Hc 128
#define Wc 128
#define Cc 192
#define NHc 6
#define WSc 16
#define SSc 8
#define Nc 256
#define HDc 32
#define NPIX (Bc*Hc*Wc)            // 65536
#define ATT_SCALE 0.17677669529663687f

#define AP 40       // A smem row stride (bf16 elems)
#define BP2 72      // B smem row stride
#define QP 40       // attention smem row stride

// ---------------- scratch (device globals) -----------------------------------
__device__ bf16  g_xnb [NPIX*Cc];
__device__ bf16  g_qkvb[(size_t)NPIX*3*Cc];
__device__ bf16  g_atb [NPIX*Cc];
__device__ bf16  g_cv1b[NPIX*64];
__device__ bf16  g_cv2b[NPIX*Cc];
__device__ float g_y   [NPIX*Cc];
__device__ bf16  g_ynb [NPIX*Cc];
__device__ bf16  g_hb  [(size_t)NPIX*4*Cc];
__device__ float g_pp  [Bc*64*Cc];
__device__ float g_ca  [Bc*Cc];
__device__ bf16  g_btb [NHc*Nc*Nc];
__device__ bf16  g_wqkv [Cc*3*Cc];
__device__ bf16  g_wproj[Cc*Cc];
__device__ bf16  g_wfc1 [Cc*4*Cc];
__device__ bf16  g_wfc2 [4*Cc*Cc];
__device__ bf16  g_wc1  [9*Cc*64];
__device__ bf16  g_wc2  [9*64*Cc];

__device__ __forceinline__ float gelu_exact(float x) {
    return 0.5f * x * (1.f + erff(x * 0.70710678118654752f));
}

// ---------------- ptx helpers ------------------------------------------------
#define CP16(dst, src) asm volatile("cp.async.cg.shared.global [%0], [%1], 16;\n" :: "r"(dst), "l"(src))
#define CP16Z(dst, src, sz) asm volatile("cp.async.cg.shared.global [%0], [%1], 16, %2;\n" :: "r"(dst), "l"(src), "r"(sz))
#define CP_COMMIT asm volatile("cp.async.commit_group;\n")
#define CP_WAITG1 asm volatile("cp.async.wait_group 1;\n")

__device__ __forceinline__ void ldsm4(uint32_t* r, uint32_t a) {
    asm volatile("ldmatrix.sync.aligned.m8n8.x4.shared.b16 {%0,%1,%2,%3},[%4];"
        : "=r"(r[0]), "=r"(r[1]), "=r"(r[2]), "=r"(r[3]) : "r"(a));
}
__device__ __forceinline__ void ldsm4t(uint32_t* r, uint32_t a) {
    asm volatile("ldmatrix.sync.aligned.m8n8.x4.trans.shared.b16 {%0,%1,%2,%3},[%4];"
        : "=r"(r[0]), "=r"(r[1]), "=r"(r[2]), "=r"(r[3]) : "r"(a));
}
__device__ __forceinline__ void mma_bf16(float* c, const uint32_t* a, const uint32_t* b) {
    asm volatile(
        "mma.sync.aligned.m16n8k16.row.col.f32.bf16.bf16.f32 "
        "{%0,%1,%2,%3}, {%4,%5,%6,%7}, {%8,%9}, {%0,%1,%2,%3};\n"
        : "+f"(c[0]), "+f"(c[1]), "+f"(c[2]), "+f"(c[3])
        : "r"(a[0]), "r"(a[1]), "r"(a[2]), "r"(a[3]), "r"(b[0]), "r"(b[1]));
}
__device__ __forceinline__ uint32_t pkbf2(float a, float b) {
    __nv_bfloat162 t = __floats2bfloat162_rn(a, b);
    return *(uint32_t*)&t;
}

// ---------------- batched weight convert --------------------------------------
#define S0 110592
#define S1 36864
#define S2 147456
#define S3 147456
#define S4 110592
#define S5 110592
#define STOT (S0+S1+S2+S3+S4+S5)
__global__ void f2b_all(const float* __restrict__ a0, const float* __restrict__ a1,
                        const float* __restrict__ a2, const float* __restrict__ a3,
                        const float* __restrict__ a4, const float* __restrict__ a5,
                        bf16* o0, bf16* o1, bf16* o2, bf16* o3, bf16* o4, bf16* o5) {
    int i = blockIdx.x * 256 + threadIdx.x;
    if (i >= STOT) return;
    if (i < S0)                { o0[i] = __float2bfloat16(a0[i]); return; }
    i -= S0;
    if (i < S1)                { o1[i] = __float2bfloat16(a1[i]); return; }
    i -= S1;
    if (i < S2)                { o2[i] = __float2bfloat16(a2[i]); return; }
    i -= S2;
    if (i < S3)                { o3[i] = __float2bfloat16(a3[i]); return; }
    i -= S3;
    if (i < S4)                { o4[i] = __float2bfloat16(a4[i]); return; }
    i -= S4;
    o5[i] = __float2bfloat16(a5[i]);
}

__global__ void btb_kernel(const float* __restrict__ rpb, const int* __restrict__ rpi,
                           bf16* __restrict__ btb) {
    int idx = blockIdx.x * 256 + threadIdx.x;
    int h = idx >> 16;
    int qk = idx & 65535;
    btb[idx] = __float2bfloat16(rpb[rpi[qk]*NHc + h]);
}

// ---------------- LayerNorm: warp per token ----------------------------------
__global__ __launch_bounds__(256) void ln_kernel(
        const float* __restrict__ x, const float* __restrict__ g,
        const float* __restrict__ b, bf16* __restrict__ out) {
    int t = (blockIdx.x * 256 + threadIdx.x) >> 5;
    int lane = threadIdx.x & 31;
    const float* row = x + (size_t)t * Cc;
    float v[6], s = 0.f, ss = 0.f;
    #pragma unroll
    for (int i = 0; i < 6; i++) {
        v[i] = row[i*32 + lane];
        s += v[i]; ss += v[i]*v[i];
    }
    #pragma unroll
    for (int o = 16; o; o >>= 1) {
        s  += __shfl_xor_sync(0xffffffffu, s, o);
        ss += __shfl_xor_sync(0xffffffffu, ss, o);
    }
    float m = s * (1.f/Cc);
    float inv = rsqrtf(ss * (1.f/Cc) - m*m + 1e-5f);
    #pragma unroll
    for (int i = 0; i < 6; i++) {
        int c = i*32 + lane;
        out[(size_t)t*Cc + c] = __float2bfloat16((v[i] - m)*inv*g[c] + b[c]);
    }
}

// ---------------- MMA compute on one staged chunk (precomputed offsets) ------
__device__ __forceinline__ void mma_stage(uint32_t ab, uint32_t bb,
        const uint32_t aoff[2][2], const uint32_t boff[2][2], float acc[2][4][4]) {
    #pragma unroll
    for (int kk = 0; kk < 2; kk++) {
        uint32_t af[2][4], bq[2][4];
        ldsm4(af[0], ab + aoff[0][kk]);
        ldsm4(af[1], ab + aoff[1][kk]);
        ldsm4t(bq[0], bb + boff[kk][0]);
        ldsm4t(bq[1], bb + boff[kk][1]);
        #pragma unroll
        for (int mi = 0; mi < 2; mi++) {
            mma_bf16(acc[mi][0], af[mi], &bq[0][0]);
            mma_bf16(acc[mi][1], af[mi], &bq[0][2]);
            mma_bf16(acc[mi][2], af[mi], &bq[1][0]);
            mma_bf16(acc[mi][3], af[mi], &bq[1][2]);
        }
    }
}

// precompute ldsm byte-offsets (relative to stage base)
__device__ __forceinline__ void mk_mma_offs(int wm, int wn, int lane,
        uint32_t aoff[2][2], uint32_t boff[2][2]) {
    #pragma unroll
    for (int mi = 0; mi < 2; mi++)
        #pragma unroll
        for (int kk = 0; kk < 2; kk++) {
            int r = wm*32 + mi*16 + (lane & 15);
            int ko = kk*16 + ((lane >> 4) << 3);
            aoff[mi][kk] = (uint32_t)((r*AP + ko) * 2);
        }
    #pragma unroll
    for (int kk = 0; kk < 2; kk++)
        #pragma unroll
        for (int nh = 0; nh < 2; nh++) {
            int krow = kk*16 + (lane & 7) + (lane & 8);
            int ncol = wn*32 + nh*16 + ((lane >> 4) << 3);
            boff[kk][nh] = (uint32_t)((krow*BP2 + ncol) * 2);
        }
}

// ---------------- GEMM: MODE 0 bf16; 1 gelu bf16; 2 fp32+res; 3 proj-combine -
template<int MODE, int GATHER, int K, int N>
__global__ __launch_bounds__(256, 3) void mma_gemm(
        const bf16* __restrict__ A, const bf16* __restrict__ W,
        const float* __restrict__ bias, void* __restrict__ Cout_,
        const float* __restrict__ Rres, const float* __restrict__ xres,
        const bf16* __restrict__ cv2b, const float* __restrict__ cab) {
    __shared__ __align__(16) bf16 As[3][128*AP];
    __shared__ __align__(16) bf16 Bs[3][32*BP2];
    constexpr int nk = K >> 5;
    constexpr uint32_t AS_ST = 128*AP*2;
    constexpr uint32_t BS_ST = 32*BP2*2;
    int tid = threadIdx.x;
    int m0 = blockIdx.x * 128, n0 = blockIdx.y * 64;
    int warp = tid >> 5, lane = tid & 31;
    int wm = warp & 3, wn = warp >> 2;
    int g = lane >> 2, tg = lane & 3;

    // hoisted A-load addressing: rows rb, rb+64 ; chunk-local col group kc*8 (0..24)
    int rb = tid >> 2, kc = tid & 3;
    const bf16* srcA[2];
    uint32_t dofA[2];
    #pragma unroll
    for (int i = 0; i < 2; i++) {
        int r = rb + i*64;
        int row;
        if (GATHER) {
            int t = m0 + r; int n = t & 255, win = t >> 8;
            int b = win >> 6, wl = win & 63;
            int hh = (((wl >> 3) << 4) + (n >> 4) + SSc) & 127;
            int ww = (((wl & 7) << 4) + (n & 15) + SSc) & 127;
            row = (b*Hc + hh)*Wc + ww;
        } else row = m0 + r;
        srcA[i] = A + (size_t)row*K + kc*8;
        dofA[i] = (uint32_t)((r*AP + kc*8) * 2);
    }
    // B-load: 32 k-rows x 8 col-groups, 1 load per thread
    int rbB = tid >> 3, kcB = tid & 7;
    const bf16* srcB = W + (size_t)rbB*N + n0 + kcB*8;
    uint32_t dofB = (uint32_t)((rbB*BP2 + kcB*8) * 2);

    uint32_t asb = (uint32_t)__cvta_generic_to_shared(&As[0][0]);
    uint32_t bsb = (uint32_t)__cvta_generic_to_shared(&Bs[0][0]);
    uint32_t aoff[2][2], boff[2][2];
    mk_mma_offs(wm, wn, lane, aoff, boff);

    float acc[2][4][4];
    #pragma unroll
    for (int a = 0; a < 2; a++)
        #pragma unroll
        for (int b = 0; b < 4; b++)
            #pragma unroll
            for (int c = 0; c < 4; c++) acc[a][b][c] = 0.f;

    auto loadAB = [&](int st, int k0) {
        uint32_t ab = asb + st*AS_ST, bb = bsb + st*BS_ST;
        CP16(ab + dofA[0], srcA[0] + k0);
        CP16(ab + dofA[1], srcA[1] + k0);
        CP16(bb + dofB, srcB + (size_t)k0*N);
    };

    loadAB(0, 0); CP_COMMIT;
    if (nk > 1) loadAB(1, 32);
    CP_COMMIT;

    int sl = 0;
    for (int c = 0; c < nk; c++) {
        CP_WAITG1;
        __syncthreads();
        int nx = c + 2;
        int sn = sl + 2; if (sn >= 3) sn -= 3;
        if (nx < nk) loadAB(sn, nx*32);
        CP_COMMIT;
        mma_stage(asb + sl*AS_ST, bsb + sl*BS_ST, aoff, boff, acc);
        if (++sl == 3) sl = 0;
    }

    #pragma unroll
    for (int mi = 0; mi < 2; mi++) {
        #pragma unroll
        for (int nj = 0; nj < 4; nj++) {
            int r1 = m0 + wm*32 + mi*16 + g;
            int r2 = r1 + 8;
            int cg = n0 + wn*32 + nj*8 + tg*2;
            float b0 = bias[cg], b1 = bias[cg+1];
            float v00 = acc[mi][nj][0] + b0, v01 = acc[mi][nj][1] + b1;
            float v10 = acc[mi][nj][2] + b0, v11 = acc[mi][nj][3] + b1;
            if (MODE == 0) {
                bf16* C = (bf16*)Cout_;
                *(__nv_bfloat162*)(C + (size_t)r1*N + cg) = __floats2bfloat162_rn(v00, v01);
                *(__nv_bfloat162*)(C + (size_t)r2*N + cg) = __floats2bfloat162_rn(v10, v11);
            } else if (MODE == 1) {
                bf16* C = (bf16*)Cout_;
                *(__nv_bfloat162*)(C + (size_t)r1*N + cg) =
                    __floats2bfloat162_rn(gelu_exact(v00), gelu_exact(v01));
                *(__nv_bfloat162*)(C + (size_t)r2*N + cg) =
                    __floats2bfloat162_rn(gelu_exact(v10), gelu_exact(v11));
            } else if (MODE == 2) {
                float* C = (float*)Cout_;
                float2 ra = *(const float2*)(Rres + (size_t)r1*N + cg);
                float2 rb2 = *(const float2*)(Rres + (size_t)r2*N + cg);
                *(float2*)(C + (size_t)r1*N + cg) = make_float2(v00+ra.x, v01+ra.y);
                *(float2*)(C + (size_t)r2*N + cg) = make_float2(v10+rb2.x, v11+rb2.y);
            } else {
                float* Y = (float*)Cout_;
                int rr[2] = {r1, r2};
                float vv[2][2] = {{v00, v01}, {v10, v11}};
                #pragma unroll
                for (int q = 0; q < 2; q++) {
                    int t = rr[q];
                    int n = t & 255, win = t >> 8;
                    int b = win >> 6, wl = win & 63;
                    int hh = ((wl >> 3) << 4) + (n >> 4);
                    int ww = ((wl & 7) << 4) + (n & 15);
                    int oh = (hh + SSc) & 127, ow = (ww + SSc) & 127;
                    size_t p = (size_t)((b*Hc + oh)*Wc + ow);
                    float2 xv = *(const float2*)(xres + p*Cc + cg);
                    float2 cav = *(const float2*)(cab + b*Cc + cg);
                    float2 cvv = __bfloat1622float2(*(const __nv_bfloat162*)(cv2b + p*Cc + cg));
                    *(float2*)(Y + p*Cc + cg) = make_float2(
                        xv.x + vv[q][0] + cvv.x*cav.x*0.01f,
                        xv.y + vv[q][1] + cvv.y*cav.y*0.01f);
                }
            }
        }
    }
}

// ---------------- 3x3 conv (implicit GEMM, hoisted addressing) ----------------
template<int MODE, int Cin, int Cout>
__global__ __launch_bounds__(256, 3) void mma_conv(
        const bf16* __restrict__ X, const bf16* __restrict__ Wt,
        const float* __restrict__ bias, bf16* __restrict__ Y) {
    __shared__ __align__(16) bf16 As[3][128*AP];
    __shared__ __align__(16) bf16 Bs[3][32*BP2];
    constexpr int CCH = Cin >> 5;
    constexpr int nk = 9 * CCH;
    constexpr uint32_t AS_ST = 128*AP*2;
    constexpr uint32_t BS_ST = 32*BP2*2;
    int bi = blockIdx.x;
    int b = bi >> 7, h = bi & 127;
    int n0 = blockIdx.y * 64;
    int tid = threadIdx.x;
    int warp = tid >> 5, lane = tid & 31;
    int wm = warp & 3, wn = warp >> 2;
    int g = lane >> 2, tg = lane & 3;

    // A-load: 2 rows per thread (rb2, rb2+64), kc4 = chunk-local 8-elem group
    int rb2 = tid >> 2, kc4 = tid & 3;
    uint32_t dofA[2];
    dofA[0] = (uint32_t)((rb2*AP + kc4*8) * 2);
    dofA[1] = (uint32_t)(((rb2+64)*AP + kc4*8) * 2);
    // per-dh row bases (clamped) + ok flags
    const bf16* rowbase[3];
    bool okH[3];
    #pragma unroll
    for (int d = 0; d < 3; d++) {
        int ih = h + d - 1;
        okH[d] = (ih >= 0 && ih < Hc);
        int ihc = min(max(ih, 0), Hc-1);
        rowbase[d] = X + (size_t)((b*Hc + ihc)*Wc) * Cin + kc4*8;
    }
    // per-dw column offsets + ok flags for this thread's 2 rows
    int iwc[3][2]; bool okW[3][2];
    #pragma unroll
    for (int d = 0; d < 3; d++)
        #pragma unroll
        for (int i = 0; i < 2; i++) {
            int r = rb2 + i*64;
            int iw = r + d - 1;
            okW[d][i] = (iw >= 0 && iw < Wc);
            iwc[d][i] = min(max(iw, 0), Wc-1);
        }
    // B: linear in global k = chunk*32 + kb
    const bf16* srcB = Wt + (size_t)(tid >> 3)*Cout + n0 + (tid & 7)*8;
    uint32_t dofB = (uint32_t)(((tid >> 3)*BP2 + (tid & 7)*8) * 2);

    uint32_t asb = (uint32_t)__cvta_generic_to_shared(&As[0][0]);
    uint32_t bsb = (uint32_t)__cvta_generic_to_shared(&Bs[0][0]);
    uint32_t aoff[2][2], boff[2][2];
    mk_mma_offs(wm, wn, lane, aoff, boff);

    float acc[2][4][4];
    #pragma unroll
    for (int a = 0; a < 2; a++)
        #pragma unroll
        for (int bb = 0; bb < 4; bb++)
            #pragma unroll
            for (int c = 0; c < 4; c++) acc[a][bb][c] = 0.f;

    auto loadAB = [&](int st, int chunk) {
        int tap = chunk / CCH;           // compile-time divisor
        int ci0 = (chunk - tap*CCH) * 32;
        int dh = tap/3, dw = tap - dh*3; // 0..2 each
        uint32_t ab = asb + st*AS_ST, bb = bsb + st*BS_ST;
        const bf16* rbp = rowbase[dh] + ci0;
        #pragma unroll
        for (int i = 0; i < 2; i++) {
            int sz = (okH[dh] && okW[dw][i]) ? 16 : 0;
            CP16Z(ab + dofA[i], rbp + (size_t)iwc[dw][i]*Cin, sz);
        }
        CP16(bb + dofB, srcB + (size_t)chunk*32*Cout);
    };

    loadAB(0, 0); CP_COMMIT;
    loadAB(1, 1); CP_COMMIT;

    int sl = 0;
    for (int c = 0; c < nk; c++) {
        CP_WAITG1;
        __syncthreads();
        int nx = c + 2;
        int sn = sl + 2; if (sn >= 3) sn -= 3;
        if (nx < nk) loadAB(sn, nx);
        CP_COMMIT;
        mma_stage(asb + sl*AS_ST, bsb + sl*BS_ST, aoff, boff, acc);
        if (++sl == 3) sl = 0;
    }

    #pragma unroll
    for (int mi = 0; mi < 2; mi++) {
        #pragma unroll
        for (int nj = 0; nj < 4; nj++) {
            int p1 = (b*Hc + h)*Wc + wm*32 + mi*16 + g;
            int p2 = p1 + 8;
            int cg = n0 + wn*32 + nj*8 + tg*2;
            float b0 = bias[cg], b1 = bias[cg+1];
            float v00 = acc[mi][nj][0] + b0, v01 = acc[mi][nj][1] + b1;
            float v10 = acc[mi][nj][2] + b0, v11 = acc[mi][nj][3] + b1;
            if (MODE == 1) {
                v00 = gelu_exact(v00); v01 = gelu_exact(v01);
                v10 = gelu_exact(v10); v11 = gelu_exact(v11);
            }
            *(__nv_bfloat162*)(Y + (size_t)p1*Cout + cg) = __floats2bfloat162_rn(v00, v01);
            *(__nv_bfloat162*)(Y + (size_t)p2*Cout + cg) = __floats2bfloat162_rn(v10, v11);
        }
    }
}

// ---------------- pool + channel attention -----------------------------------
__global__ void pool_kernel(const bf16* __restrict__ cv2b, float* __restrict__ pp) {
    int blk = blockIdx.x;
    int b = blk >> 6, chunk = blk & 63;
    int c = threadIdx.x;
    float s = 0.f;
    int base = b*16384 + chunk*256;
    for (int p = 0; p < 256; p++) s += __bfloat162float(cv2b[(size_t)(base + p)*Cc + c]);
    pp[blk*Cc + c] = s;
}

__global__ void ca_kernel(const float* __restrict__ pp,
                          const float* __restrict__ w1, const float* __restrict__ b1,
                          const float* __restrict__ w2, const float* __restrict__ b2,
                          float* __restrict__ ca) {
    __shared__ float pooled[Bc*Cc];
    __shared__ float t1[Bc*6];
    int tid = threadIdx.x;
    for (int i = tid; i < Bc*Cc; i += 256) {
        int b = i / Cc, c = i % Cc;
        float s = 0.f;
        for (int j = 0; j < 64; j++) s += pp[(b*64 + j)*Cc + c];
        pooled[i] = s * (1.f/16384.f);
    }
    __syncthreads();
    if (tid < Bc*6) {
        int b = tid / 6, j = tid % 6;
        float s = b1[j];
        for (int c = 0; c < Cc; c++) s += pooled[b*Cc + c] * w1[c*6 + j];
        t1[tid] = fmaxf(s, 0.f);
    }
    __syncthreads();
    for (int i = tid; i < Bc*Cc; i += 256) {
        int b = i / Cc, c = i % Cc;
        float s = b2[c];
        #pragma unroll
        for (int j = 0; j < 6; j++) s += t1[b*6 + j] * w2[j*Cc + c];
        ca[i] = 1.f / (1.f + expf(-s));
    }
}

// ---------------- flash window attention via tensor-core MMA ------------------
__global__ __launch_bounds__(256) void attn_mma(
        const bf16* __restrict__ qkvb, const bf16* __restrict__ btb,
        bf16* __restrict__ out) {
    extern __shared__ __align__(16) bf16 smA[];
    bf16* Qs = smA;
    bf16* Ks = smA + 256*QP;
    bf16* Vs = smA + 2*256*QP;
    int win = blockIdx.x, h = blockIdx.y;
    int tid = threadIdx.x;
    int warp = tid >> 5, lane = tid & 31;
    int g = lane >> 2, tg = lane & 3;
    int m0 = warp * 32;

    {
        const uint4* src = (const uint4*)(qkvb + (size_t)(win*Nc + tid)*576 + h*HDc);
        uint4* qd = (uint4*)(Qs + tid*QP);
        uint4* kd = (uint4*)(Ks + tid*QP);
        uint4* vd = (uint4*)(Vs + tid*QP);
        #pragma unroll
        for (int i = 0; i < 4; i++) {
            qd[i] = src[i];
            kd[i] = src[i + 24];
            vd[i] = src[i + 48];
        }
    }
    __syncthreads();

    uint32_t qf[2][2][4];
    #pragma unroll
    for (int mi = 0; mi < 2; mi++)
        #pragma unroll
        for (int ks = 0; ks < 2; ks++) {
            int r = m0 + mi*16 + (lane & 15);
            int kofs = ks*16 + ((lane >> 4) << 3);
            ldsm4(qf[mi][ks], (uint32_t)__cvta_generic_to_shared(Qs + r*QP + kofs));
        }

    const bf16* cb = btb + ((size_t)h << 16);

    int wl = win & 63;
    bool er = (wl >> 3) == 7, ec = (wl & 7) == 7;
    bool edge = er || ec;
    int lq[2][2];
    #pragma unroll
    for (int mi = 0; mi < 2; mi++)
        #pragma unroll
        for (int rh = 0; rh < 2; rh++) {
            int q = m0 + mi*16 + g + rh*8;
            int rc = er ? (((q >> 4) < 8) ? 1 : 2) : 0;
            int cc = ec ? (((q & 15) < 8) ? 1 : 2) : 0;
            lq[mi][rh] = rc*3 + cc;
        }

    float mx[2][2], lsum[2][2];
    float o[2][4][4];
    #pragma unroll
    for (int mi = 0; mi < 2; mi++)
        #pragma unroll
        for (int rh = 0; rh < 2; rh++) { mx[mi][rh] = -1e30f; lsum[mi][rh] = 0.f; }
    #pragma unroll
    for (int mi = 0; mi < 2; mi++)
        #pragma unroll
        for (int nt = 0; nt < 4; nt++)
            #pragma unroll
            for (int e = 0; e < 4; e++) o[mi][nt][e] = 0.f;

    for (int c0 = 0; c0 < Nc; c0 += 32) {
        float s[2][4][4];
        #pragma unroll
        for (int mi = 0; mi < 2; mi++)
            #pragma unroll
            for (int nj = 0; nj < 4; nj++)
                #pragma unroll
                for (int e = 0; e < 4; e++) s[mi][nj][e] = 0.f;

        #pragma unroll
        for (int ks = 0; ks < 2; ks++) {
            uint32_t kf[2][4];
            #pragma unroll
            for (int np = 0; np < 2; np++) {
                int n = c0 + np*16 + (lane & 7) + ((lane >> 4) << 3);
                int kc = ks*16 + ((lane >> 3) & 1)*8;
                ldsm4(kf[np], (uint32_t)__cvta_generic_to_shared(Ks + n*QP + kc));
            }
            #pragma unroll
            for (int mi = 0; mi < 2; mi++) {
                mma_bf16(s[mi][0], qf[mi][ks], &kf[0][0]);
                mma_bf16(s[mi][1], qf[mi][ks], &kf[0][2]);
                mma_bf16(s[mi][2], qf[mi][ks], &kf[1][0]);
                mma_bf16(s[mi][3], qf[mi][ks], &kf[1][2]);
            }
        }

        int lk[4][2];
        if (edge) {
            #pragma unroll
            for (int nj = 0; nj < 4; nj++)
                #pragma unroll
                for (int e = 0; e < 2; e++) {
                    int kcol = c0 + nj*8 + tg*2 + e;
                    int rc = er ? (((kcol >> 4) < 8) ? 1 : 2) : 0;
                    int cc = ec ? (((kcol & 15) < 8) ? 1 : 2) : 0;
                    lk[nj][e] = rc*3 + cc;
                }
        }
        #pragma unroll
        for (int mi = 0; mi < 2; mi++) {
            int row0 = m0 + mi*16 + g;
            #pragma unroll
            for (int nj = 0; nj < 4; nj++) {
                int col = c0 + nj*8 + tg*2;
                float2 b0 = __bfloat1622float2(*(const __nv_bfloat162*)(cb + (size_t)row0*Nc + col));
                float2 b1 = __bfloat1622float2(*(const __nv_bfloat162*)(cb + (size_t)(row0+8)*Nc + col));
                s[mi][nj][0] = s[mi][nj][0]*ATT_SCALE + b0.x;
                s[mi][nj][1] = s[mi][nj][1]*ATT_SCALE + b0.y;
                s[mi][nj][2] = s[mi][nj][2]*ATT_SCALE + b1.x;
                s[mi][nj][3] = s[mi][nj][3]*ATT_SCALE + b1.y;
                if (edge) {
                    s[mi][nj][0] += (lq[mi][0] == lk[nj][0]) ? 0.f : -100.f;
                    s[mi][nj][1] += (lq[mi][0] == lk[nj][1]) ? 0.f : -100.f;
                    s[mi][nj][2] += (lq[mi][1] == lk[nj][0]) ? 0.f : -100.f;
                    s[mi][nj][3] += (lq[mi][1] == lk[nj][1]) ? 0.f : -100.f;
                }
            }
            #pragma unroll
            for (int rh = 0; rh < 2; rh++) {
                int e0 = rh*2;
                float m_ = fmaxf(fmaxf(s[mi][0][e0], s[mi][0][e0+1]),
                                 fmaxf(s[mi][1][e0], s[mi][1][e0+1]));
                m_ = fmaxf(m_, fmaxf(fmaxf(s[mi][2][e0], s[mi][2][e0+1]),
                                     fmaxf(s[mi][3][e0], s[mi][3][e0+1])));
                m_ = fmaxf(m_, __shfl_xor_sync(0xffffffffu, m_, 1));
                m_ = fmaxf(m_, __shfl_xor_sync(0xffffffffu, m_, 2));
                float newm = fmaxf(mx[mi][rh], m_);
                float sc = __expf(mx[mi][rh] - newm);
                mx[mi][rh] = newm;
                float ps = 0.f;
                #pragma unroll
                for (int nj = 0; nj < 4; nj++) {
                    float p0 = __expf(s[mi][nj][e0]   - newm);
                    float p1 = __expf(s[mi][nj][e0+1] - newm);
                    s[mi][nj][e0] = p0; s[mi][nj][e0+1] = p1;
                    ps += p0 + p1;
                }
                ps += __shfl_xor_sync(0xffffffffu, ps, 1);
                ps += __shfl_xor_sync(0xffffffffu, ps, 2);
                lsum[mi][rh] = lsum[mi][rh]*sc + ps;
                #pragma unroll
                for (int nt = 0; nt < 4; nt++) {
                    o[mi][nt][e0]   *= sc;
                    o[mi][nt][e0+1] *= sc;
                }
            }
        }

        #pragma unroll
        for (int ks2 = 0; ks2 < 2; ks2++) {
            uint32_t vf[2][4];
            int krow = c0 + ks2*16 + (lane & 7) + (lane & 8);
            #pragma unroll
            for (int dp = 0; dp < 2; dp++)
                ldsm4t(vf[dp], (uint32_t)__cvta_generic_to_shared(
                    Vs + krow*QP + dp*16 + ((lane >> 4) << 3)));
            #pragma unroll
            for (int mi = 0; mi < 2; mi++) {
                uint32_t af[4];
                af[0] = pkbf2(s[mi][2*ks2][0],   s[mi][2*ks2][1]);
                af[1] = pkbf2(s[mi][2*ks2][2],   s[mi][2*ks2][3]);
                af[2] = pkbf2(s[mi][2*ks2+1][0], s[mi][2*ks2+1][1]);
                af[3] = pkbf2(s[mi][2*ks2+1][2], s[mi][2*ks2+1][3]);
                mma_bf16(o[mi][0], af, &vf[0][0]);
                mma_bf16(o[mi][1], af, &vf[0][2]);
                mma_bf16(o[mi][2], af, &vf[1][0]);
                mma_bf16(o[mi][3], af, &vf[1][2]);
            }
        }
    }

    #pragma unroll
    for (int mi = 0; mi < 2; mi++) {
        #pragma unroll
        for (int rh = 0; rh < 2; rh++) {
            float inv = 1.f / lsum[mi][rh];
            int row = win*Nc + m0 + mi*16 + g + rh*8;
            bf16* orow = out + (size_t)row*Cc + h*HDc;
            #pragma unroll
            for (int nt = 0; nt < 4; nt++) {
                *(__nv_bfloat162*)(orow + nt*8 + tg*2) =
                    __floats2bfloat162_rn(o[mi][nt][rh*2]*inv, o[mi][nt][rh*2+1]*inv);
            }
        }
    }
}

// ---------------- launch -----------------------------------------------------
extern "C" void kernel_launch(void* const* d_in, const int* in_sizes, int n_in,
                              void* d_out, int out_size) {
    const float* x     = (const float*)d_in[0];
    const float* qkv_w = (const float*)d_in[1];
    const float* qkv_b = (const float*)d_in[2];
    const float* proj_w= (const float*)d_in[3];
    const float* proj_b= (const float*)d_in[4];
    const float* rpb   = (const float*)d_in[5];
    const float* n1w   = (const float*)d_in[6];
    const float* n1b   = (const float*)d_in[7];
    const float* n2w   = (const float*)d_in[8];
    const float* n2b   = (const float*)d_in[9];
    const float* c1w   = (const float*)d_in[10];
    const float* c1b   = (const float*)d_in[11];
    const float* c2w   = (const float*)d_in[12];
    const float* c2b   = (const float*)d_in[13];
    const float* ca1w  = (const float*)d_in[14];
    const float* ca1b  = (const float*)d_in[15];
    const float* ca2w  = (const float*)d_in[16];
    const float* ca2b  = (const float*)d_in[17];
    const float* fc1w  = (const float*)d_in[18];
    const float* fc1b  = (const float*)d_in[19];
    const float* fc2w  = (const float*)d_in[20];
    const float* fc2b  = (const float*)d_in[21];
    const int*   rpi   = (const int*)d_in[22];
    float* out = (float*)d_out;

    bf16 *xnb, *qkvb, *atb, *cv1b, *cv2b, *ynb, *hb, *btb;
    bf16 *wqkv, *wproj, *wfc1, *wfc2, *wc1, *wc2;
    float *y, *pp, *cab;
    cudaGetSymbolAddress((void**)&xnb,  g_xnb);
    cudaGetSymbolAddress((void**)&qkvb, g_qkvb);
    cudaGetSymbolAddress((void**)&atb,  g_atb);
    cudaGetSymbolAddress((void**)&cv1b, g_cv1b);
    cudaGetSymbolAddress((void**)&cv2b, g_cv2b);
    cudaGetSymbolAddress((void**)&y,    g_y);
    cudaGetSymbolAddress((void**)&ynb,  g_ynb);
    cudaGetSymbolAddress((void**)&hb,   g_hb);
    cudaGetSymbolAddress((void**)&pp,   g_pp);
    cudaGetSymbolAddress((void**)&cab,  g_ca);
    cudaGetSymbolAddress((void**)&btb,  g_btb);
    cudaGetSymbolAddress((void**)&wqkv, g_wqkv);
    cudaGetSymbolAddress((void**)&wproj,g_wproj);
    cudaGetSymbolAddress((void**)&wfc1, g_wfc1);
    cudaGetSymbolAddress((void**)&wfc2, g_wfc2);
    cudaGetSymbolAddress((void**)&wc1,  g_wc1);
    cudaGetSymbolAddress((void**)&wc2,  g_wc2);

    static cudaStream_t sB = nullptr;
    static cudaEvent_t evFork = nullptr, evB = nullptr;
    if (!sB) {
        cudaStreamCreateWithFlags(&sB, cudaStreamNonBlocking);
        cudaEventCreateWithFlags(&evFork, cudaEventDisableTiming);
        cudaEventCreateWithFlags(&evB, cudaEventDisableTiming);
        cudaFuncSetAttribute(attn_mma, cudaFuncAttributeMaxDynamicSharedMemorySize,
                             3*256*QP*sizeof(bf16));
    }

    // prologue (main stream)
    f2b_all<<<(STOT + 255)/256, 256>>>(qkv_w, proj_w, fc1w, fc2w, c1w, c2w,
                                       wqkv, wproj, wfc1, wfc2, wc1, wc2);
    btb_kernel<<<NHc*Nc*Nc/256, 256>>>(rpb, rpi, btb);
    ln_kernel<<<NPIX/8, 256>>>(x, n1w, n1b, xnb);

    // fork: conv branch on sB, attention branch on main stream
    cudaEventRecord(evFork, 0);
    cudaStreamWaitEvent(sB, evFork, 0);
    mma_conv<1, Cc, 64><<<dim3(Bc*Hc, 1), 256, 0, sB>>>(xnb, wc1, c1b, cv1b);
    mma_conv<0, 64, Cc><<<dim3(Bc*Hc, 3), 256, 0, sB>>>(cv1b, wc2, c2b, cv2b);
    pool_kernel<<<Bc*64, Cc, 0, sB>>>(cv2b, pp);
    ca_kernel<<<1, 256, 0, sB>>>(pp, ca1w, ca1b, ca2w, ca2b, cab);
    cudaEventRecord(evB, sB);

    mma_gemm<0, 1, Cc, 3*Cc><<<dim3(NPIX/128, 9), 256>>>(xnb, wqkv, qkv_b, qkvb,
                                                         nullptr, nullptr, nullptr, nullptr);
    attn_mma<<<dim3(256, NHc), 256, 3*256*QP*sizeof(bf16)>>>(qkvb, btb, atb);

    // join: proj + window-reverse + residual combine needs conv branch
    cudaStreamWaitEvent(0, evB, 0);
    mma_gemm<3, 0, Cc, Cc><<<dim3(NPIX/128, 3), 256>>>(atb, wproj, proj_b, y,
                                                       nullptr, x, cv2b, cab);
    // MLP
    ln_kernel<<<NPIX/8, 256>>>(y, n2w, n2b, ynb);
    mma_gemm<1, 0, Cc, 4*Cc><<<dim3(NPIX/128, 12), 256>>>(ynb, wfc1, fc1b, hb,
                                                          nullptr, nullptr, nullptr, nullptr);
    mma_gemm<2, 0, 4*Cc, Cc><<<dim3(NPIX/128, 3), 256>>>(hb, wfc2, fc2b, out,
                                                         y, nullptr, nullptr, nullptr);
}

// round 16
// speedup vs baseline: 1.2736x; 1.0352x over previous
#include <cuda_runtime.h>
#include <cuda_bf16.h>
#include <math.h>
#include <stdint.h>

typedef __nv_bfloat16 bf16;

#define Bc 4
#define Hc 128
#define Wc 128
#define Cc 192
#define NHc 6
#define WSc 16
#define SSc 8
#define Nc 256
#define HDc 32
#define NPIX (Bc*Hc*Wc)            // 65536
#define ATT_SCALE 0.17677669529663687f

#define AP 40       // A smem row stride (bf16 elems)
#define BP2 72      // B smem row stride
#define QP 40       // attention smem row stride

// ---------------- scratch (device globals) -----------------------------------
__device__ bf16  g_xnb [NPIX*Cc];
__device__ bf16  g_qkvb[(size_t)NPIX*3*Cc];
__device__ bf16  g_atb [NPIX*Cc];
__device__ bf16  g_cv1b[NPIX*64];
__device__ bf16  g_cv2b[NPIX*Cc];
__device__ float g_y   [NPIX*Cc];
__device__ bf16  g_ynb [NPIX*Cc];
__device__ bf16  g_hb  [(size_t)NPIX*4*Cc];
__device__ float g_pp  [Bc*64*Cc];
__device__ float g_ca  [Bc*Cc];
__device__ bf16  g_btb [NHc*Nc*Nc];
__device__ bf16  g_wqkv [Cc*3*Cc];
__device__ bf16  g_wproj[Cc*Cc];
__device__ bf16  g_wfc1 [Cc*4*Cc];
__device__ bf16  g_wfc2 [4*Cc*Cc];
__device__ bf16  g_wc1  [9*Cc*64];
__device__ bf16  g_wc2  [9*64*Cc];

__device__ __forceinline__ float gelu_exact(float x) {
    return 0.5f * x * (1.f + erff(x * 0.70710678118654752f));
}

// ---------------- ptx helpers ------------------------------------------------
#define CP16(dst, src) asm volatile("cp.async.cg.shared.global [%0], [%1], 16;\n" :: "r"(dst), "l"(src))
#define CP16Z(dst, src, sz) asm volatile("cp.async.cg.shared.global [%0], [%1], 16, %2;\n" :: "r"(dst), "l"(src), "r"(sz))
#define CP_COMMIT asm volatile("cp.async.commit_group;\n")
#define CP_WAITG1 asm volatile("cp.async.wait_group 1;\n")

__device__ __forceinline__ void ldsm4(uint32_t* r, uint32_t a) {
    asm volatile("ldmatrix.sync.aligned.m8n8.x4.shared.b16 {%0,%1,%2,%3},[%4];"
        : "=r"(r[0]), "=r"(r[1]), "=r"(r[2]), "=r"(r[3]) : "r"(a));
}
__device__ __forceinline__ void ldsm4t(uint32_t* r, uint32_t a) {
    asm volatile("ldmatrix.sync.aligned.m8n8.x4.trans.shared.b16 {%0,%1,%2,%3},[%4];"
        : "=r"(r[0]), "=r"(r[1]), "=r"(r[2]), "=r"(r[3]) : "r"(a));
}
__device__ __forceinline__ void mma_bf16(float* c, const uint32_t* a, const uint32_t* b) {
    asm volatile(
        "mma.sync.aligned.m16n8k16.row.col.f32.bf16.bf16.f32 "
        "{%0,%1,%2,%3}, {%4,%5,%6,%7}, {%8,%9}, {%0,%1,%2,%3};\n"
        : "+f"(c[0]), "+f"(c[1]), "+f"(c[2]), "+f"(c[3])
        : "r"(a[0]), "r"(a[1]), "r"(a[2]), "r"(a[3]), "r"(b[0]), "r"(b[1]));
}
__device__ __forceinline__ uint32_t pkbf2(float a, float b) {
    __nv_bfloat162 t = __floats2bfloat162_rn(a, b);
    return *(uint32_t*)&t;
}

// ---------------- batched weight convert --------------------------------------
#define S0 110592
#define S1 36864
#define S2 147456
#define S3 147456
#define S4 110592
#define S5 110592
#define STOT (S0+S1+S2+S3+S4+S5)
__global__ void f2b_all(const float* __restrict__ a0, const float* __restrict__ a1,
                        const float* __restrict__ a2, const float* __restrict__ a3,
                        const float* __restrict__ a4, const float* __restrict__ a5,
                        bf16* o0, bf16* o1, bf16* o2, bf16* o3, bf16* o4, bf16* o5) {
    int i = blockIdx.x * 256 + threadIdx.x;
    if (i >= STOT) return;
    if (i < S0)                { o0[i] = __float2bfloat16(a0[i]); return; }
    i -= S0;
    if (i < S1)                { o1[i] = __float2bfloat16(a1[i]); return; }
    i -= S1;
    if (i < S2)                { o2[i] = __float2bfloat16(a2[i]); return; }
    i -= S2;
    if (i < S3)                { o3[i] = __float2bfloat16(a3[i]); return; }
    i -= S3;
    if (i < S4)                { o4[i] = __float2bfloat16(a4[i]); return; }
    i -= S4;
    o5[i] = __float2bfloat16(a5[i]);
}

__global__ void btb_kernel(const float* __restrict__ rpb, const int* __restrict__ rpi,
                           bf16* __restrict__ btb) {
    int idx = blockIdx.x * 256 + threadIdx.x;
    int h = idx >> 16;
    int qk = idx & 65535;
    btb[idx] = __float2bfloat16(rpb[rpi[qk]*NHc + h]);
}

// ---------------- LayerNorm: warp per token ----------------------------------
__global__ __launch_bounds__(256) void ln_kernel(
        const float* __restrict__ x, const float* __restrict__ g,
        const float* __restrict__ b, bf16* __restrict__ out) {
    int t = (blockIdx.x * 256 + threadIdx.x) >> 5;
    int lane = threadIdx.x & 31;
    const float* row = x + (size_t)t * Cc;
    float v[6], s = 0.f, ss = 0.f;
    #pragma unroll
    for (int i = 0; i < 6; i++) {
        v[i] = row[i*32 + lane];
        s += v[i]; ss += v[i]*v[i];
    }
    #pragma unroll
    for (int o = 16; o; o >>= 1) {
        s  += __shfl_xor_sync(0xffffffffu, s, o);
        ss += __shfl_xor_sync(0xffffffffu, ss, o);
    }
    float m = s * (1.f/Cc);
    float inv = rsqrtf(ss * (1.f/Cc) - m*m + 1e-5f);
    #pragma unroll
    for (int i = 0; i < 6; i++) {
        int c = i*32 + lane;
        out[(size_t)t*Cc + c] = __float2bfloat16((v[i] - m)*inv*g[c] + b[c]);
    }
}

// ---------------- MMA compute on one staged chunk (precomputed offsets) ------
__device__ __forceinline__ void mma_stage(uint32_t ab, uint32_t bb,
        const uint32_t aoff[2][2], const uint32_t boff[2][2], float acc[2][4][4]) {
    #pragma unroll
    for (int kk = 0; kk < 2; kk++) {
        uint32_t af[2][4], bq[2][4];
        ldsm4(af[0], ab + aoff[0][kk]);
        ldsm4(af[1], ab + aoff[1][kk]);
        ldsm4t(bq[0], bb + boff[kk][0]);
        ldsm4t(bq[1], bb + boff[kk][1]);
        #pragma unroll
        for (int mi = 0; mi < 2; mi++) {
            mma_bf16(acc[mi][0], af[mi], &bq[0][0]);
            mma_bf16(acc[mi][1], af[mi], &bq[0][2]);
            mma_bf16(acc[mi][2], af[mi], &bq[1][0]);
            mma_bf16(acc[mi][3], af[mi], &bq[1][2]);
        }
    }
}

// precompute ldsm byte-offsets (relative to stage base)
__device__ __forceinline__ void mk_mma_offs(int wm, int wn, int lane,
        uint32_t aoff[2][2], uint32_t boff[2][2]) {
    #pragma unroll
    for (int mi = 0; mi < 2; mi++)
        #pragma unroll
        for (int kk = 0; kk < 2; kk++) {
            int r = wm*32 + mi*16 + (lane & 15);
            int ko = kk*16 + ((lane >> 4) << 3);
            aoff[mi][kk] = (uint32_t)((r*AP + ko) * 2);
        }
    #pragma unroll
    for (int kk = 0; kk < 2; kk++)
        #pragma unroll
        for (int nh = 0; nh < 2; nh++) {
            int krow = kk*16 + (lane & 7) + (lane & 8);
            int ncol = wn*32 + nh*16 + ((lane >> 4) << 3);
            boff[kk][nh] = (uint32_t)((krow*BP2 + ncol) * 2);
        }
}

// ---------------- GEMM: MODE 0 bf16; 1 gelu bf16; 2 fp32+res; 3 proj-combine -
template<int MODE, int GATHER, int K, int N>
__global__ __launch_bounds__(256, 3) void mma_gemm(
        const bf16* __restrict__ A, const bf16* __restrict__ W,
        const float* __restrict__ bias, void* __restrict__ Cout_,
        const float* __restrict__ Rres, const float* __restrict__ xres,
        const bf16* __restrict__ cv2b, const float* __restrict__ cab) {
    __shared__ __align__(16) bf16 As[3][128*AP];
    __shared__ __align__(16) bf16 Bs[3][32*BP2];
    constexpr int nk = K >> 5;
    constexpr uint32_t AS_ST = 128*AP*2;
    constexpr uint32_t BS_ST = 32*BP2*2;
    int tid = threadIdx.x;
    int m0 = blockIdx.x * 128, n0 = blockIdx.y * 64;
    int warp = tid >> 5, lane = tid & 31;
    int wm = warp & 3, wn = warp >> 2;
    int g = lane >> 2, tg = lane & 3;

    int rb = tid >> 2, kc = tid & 3;
    const bf16* srcA[2];
    uint32_t dofA[2];
    #pragma unroll
    for (int i = 0; i < 2; i++) {
        int r = rb + i*64;
        int row;
        if (GATHER) {
            int t = m0 + r; int n = t & 255, win = t >> 8;
            int b = win >> 6, wl = win & 63;
            int hh = (((wl >> 3) << 4) + (n >> 4) + SSc) & 127;
            int ww = (((wl & 7) << 4) + (n & 15) + SSc) & 127;
            row = (b*Hc + hh)*Wc + ww;
        } else row = m0 + r;
        srcA[i] = A + (size_t)row*K + kc*8;
        dofA[i] = (uint32_t)((r*AP + kc*8) * 2);
    }
    int rbB = tid >> 3, kcB = tid & 7;
    const bf16* srcB = W + (size_t)rbB*N + n0 + kcB*8;
    uint32_t dofB = (uint32_t)((rbB*BP2 + kcB*8) * 2);

    uint32_t asb = (uint32_t)__cvta_generic_to_shared(&As[0][0]);
    uint32_t bsb = (uint32_t)__cvta_generic_to_shared(&Bs[0][0]);
    uint32_t aoff[2][2], boff[2][2];
    mk_mma_offs(wm, wn, lane, aoff, boff);

    float acc[2][4][4];
    #pragma unroll
    for (int a = 0; a < 2; a++)
        #pragma unroll
        for (int b = 0; b < 4; b++)
            #pragma unroll
            for (int c = 0; c < 4; c++) acc[a][b][c] = 0.f;

    auto loadAB = [&](int st, int k0) {
        uint32_t ab = asb + st*AS_ST, bb = bsb + st*BS_ST;
        CP16(ab + dofA[0], srcA[0] + k0);
        CP16(ab + dofA[1], srcA[1] + k0);
        CP16(bb + dofB, srcB + (size_t)k0*N);
    };

    loadAB(0, 0); CP_COMMIT;
    if (nk > 1) loadAB(1, 32);
    CP_COMMIT;

    #pragma unroll
    for (int c = 0; c < nk; c++) {
        CP_WAITG1;
        __syncthreads();
        int nx = c + 2;
        int sl = c % 3;
        int sn = nx % 3;
        if (nx < nk) loadAB(sn, nx*32);
        CP_COMMIT;
        mma_stage(asb + sl*AS_ST, bsb + sl*BS_ST, aoff, boff, acc);
    }

    #pragma unroll
    for (int mi = 0; mi < 2; mi++) {
        #pragma unroll
        for (int nj = 0; nj < 4; nj++) {
            int r1 = m0 + wm*32 + mi*16 + g;
            int r2 = r1 + 8;
            int cg = n0 + wn*32 + nj*8 + tg*2;
            float b0 = bias[cg], b1 = bias[cg+1];
            float v00 = acc[mi][nj][0] + b0, v01 = acc[mi][nj][1] + b1;
            float v10 = acc[mi][nj][2] + b0, v11 = acc[mi][nj][3] + b1;
            if (MODE == 0) {
                bf16* C = (bf16*)Cout_;
                *(__nv_bfloat162*)(C + (size_t)r1*N + cg) = __floats2bfloat162_rn(v00, v01);
                *(__nv_bfloat162*)(C + (size_t)r2*N + cg) = __floats2bfloat162_rn(v10, v11);
            } else if (MODE == 1) {
                bf16* C = (bf16*)Cout_;
                *(__nv_bfloat162*)(C + (size_t)r1*N + cg) =
                    __floats2bfloat162_rn(gelu_exact(v00), gelu_exact(v01));
                *(__nv_bfloat162*)(C + (size_t)r2*N + cg) =
                    __floats2bfloat162_rn(gelu_exact(v10), gelu_exact(v11));
            } else if (MODE == 2) {
                float* C = (float*)Cout_;
                float2 ra = *(const float2*)(Rres + (size_t)r1*N + cg);
                float2 rb2 = *(const float2*)(Rres + (size_t)r2*N + cg);
                *(float2*)(C + (size_t)r1*N + cg) = make_float2(v00+ra.x, v01+ra.y);
                *(float2*)(C + (size_t)r2*N + cg) = make_float2(v10+rb2.x, v11+rb2.y);
            } else {
                float* Y = (float*)Cout_;
                int rr[2] = {r1, r2};
                float vv[2][2] = {{v00, v01}, {v10, v11}};
                #pragma unroll
                for (int q = 0; q < 2; q++) {
                    int t = rr[q];
                    int n = t & 255, win = t >> 8;
                    int b = win >> 6, wl = win & 63;
                    int hh = ((wl >> 3) << 4) + (n >> 4);
                    int ww = ((wl & 7) << 4) + (n & 15);
                    int oh = (hh + SSc) & 127, ow = (ww + SSc) & 127;
                    size_t p = (size_t)((b*Hc + oh)*Wc + ow);
                    float2 xv = *(const float2*)(xres + p*Cc + cg);
                    float2 cav = *(const float2*)(cab + b*Cc + cg);
                    float2 cvv = __bfloat1622float2(*(const __nv_bfloat162*)(cv2b + p*Cc + cg));
                    *(float2*)(Y + p*Cc + cg) = make_float2(
                        xv.x + vv[q][0] + cvv.x*cav.x*0.01f,
                        xv.y + vv[q][1] + cvv.y*cav.y*0.01f);
                }
            }
        }
    }
}

// ---------------- 3x3 conv (implicit GEMM, fully unrolled k-loop) -------------
template<int MODE, int Cin, int Cout>
__global__ __launch_bounds__(256, 3) void mma_conv(
        const bf16* __restrict__ X, const bf16* __restrict__ Wt,
        const float* __restrict__ bias, bf16* __restrict__ Y) {
    __shared__ __align__(16) bf16 As[3][128*AP];
    __shared__ __align__(16) bf16 Bs[3][32*BP2];
    constexpr int CCH = Cin >> 5;
    constexpr int nk = 9 * CCH;
    constexpr uint32_t AS_ST = 128*AP*2;
    constexpr uint32_t BS_ST = 32*BP2*2;
    int bi = blockIdx.x;
    int b = bi >> 7, h = bi & 127;
    int n0 = blockIdx.y * 64;
    int tid = threadIdx.x;
    int warp = tid >> 5, lane = tid & 31;
    int wm = warp & 3, wn = warp >> 2;
    int g = lane >> 2, tg = lane & 3;

    int rb2 = tid >> 2, kc4 = tid & 3;
    uint32_t dofA[2];
    dofA[0] = (uint32_t)((rb2*AP + kc4*8) * 2);
    dofA[1] = (uint32_t)(((rb2+64)*AP + kc4*8) * 2);
    const bf16* rowbase[3];
    bool okH[3];
    #pragma unroll
    for (int d = 0; d < 3; d++) {
        int ih = h + d - 1;
        okH[d] = (ih >= 0 && ih < Hc);
        int ihc = min(max(ih, 0), Hc-1);
        rowbase[d] = X + (size_t)((b*Hc + ihc)*Wc) * Cin + kc4*8;
    }
    int iwc[3][2]; bool okW[3][2];
    #pragma unroll
    for (int d = 0; d < 3; d++)
        #pragma unroll
        for (int i = 0; i < 2; i++) {
            int r = rb2 + i*64;
            int iw = r + d - 1;
            okW[d][i] = (iw >= 0 && iw < Wc);
            iwc[d][i] = min(max(iw, 0), Wc-1);
        }
    const bf16* srcB = Wt + (size_t)(tid >> 3)*Cout + n0 + (tid & 7)*8;
    uint32_t dofB = (uint32_t)(((tid >> 3)*BP2 + (tid & 7)*8) * 2);

    uint32_t asb = (uint32_t)__cvta_generic_to_shared(&As[0][0]);
    uint32_t bsb = (uint32_t)__cvta_generic_to_shared(&Bs[0][0]);
    uint32_t aoff[2][2], boff[2][2];
    mk_mma_offs(wm, wn, lane, aoff, boff);

    float acc[2][4][4];
    #pragma unroll
    for (int a = 0; a < 2; a++)
        #pragma unroll
        for (int bb = 0; bb < 4; bb++)
            #pragma unroll
            for (int c = 0; c < 4; c++) acc[a][bb][c] = 0.f;

    auto loadAB = [&](int st, int chunk) {
        int tap = chunk / CCH;
        int ci0 = (chunk - tap*CCH) * 32;
        int dh = tap/3, dw = tap - dh*3;
        uint32_t ab = asb + st*AS_ST, bb = bsb + st*BS_ST;
        const bf16* rbp = rowbase[dh] + ci0;
        #pragma unroll
        for (int i = 0; i < 2; i++) {
            int sz = (okH[dh] && okW[dw][i]) ? 16 : 0;
            CP16Z(ab + dofA[i], rbp + (size_t)iwc[dw][i]*Cin, sz);
        }
        CP16(bb + dofB, srcB + (size_t)chunk*32*Cout);
    };

    loadAB(0, 0); CP_COMMIT;
    loadAB(1, 1); CP_COMMIT;

    #pragma unroll
    for (int c = 0; c < nk; c++) {
        CP_WAITG1;
        __syncthreads();
        int nx = c + 2;
        int sl = c % 3;
        int sn = nx % 3;
        if (nx < nk) loadAB(sn, nx);
        CP_COMMIT;
        mma_stage(asb + sl*AS_ST, bsb + sl*BS_ST, aoff, boff, acc);
    }

    #pragma unroll
    for (int mi = 0; mi < 2; mi++) {
        #pragma unroll
        for (int nj = 0; nj < 4; nj++) {
            int p1 = (b*Hc + h)*Wc + wm*32 + mi*16 + g;
            int p2 = p1 + 8;
            int cg = n0 + wn*32 + nj*8 + tg*2;
            float b0 = bias[cg], b1 = bias[cg+1];
            float v00 = acc[mi][nj][0] + b0, v01 = acc[mi][nj][1] + b1;
            float v10 = acc[mi][nj][2] + b0, v11 = acc[mi][nj][3] + b1;
            if (MODE == 1) {
                v00 = gelu_exact(v00); v01 = gelu_exact(v01);
                v10 = gelu_exact(v10); v11 = gelu_exact(v11);
            }
            *(__nv_bfloat162*)(Y + (size_t)p1*Cout + cg) = __floats2bfloat162_rn(v00, v01);
            *(__nv_bfloat162*)(Y + (size_t)p2*Cout + cg) = __floats2bfloat162_rn(v10, v11);
        }
    }
}

// ---------------- pool + channel attention -----------------------------------
__global__ void pool_kernel(const bf16* __restrict__ cv2b, float* __restrict__ pp) {
    int blk = blockIdx.x;
    int b = blk >> 6, chunk = blk & 63;
    int c = threadIdx.x;
    float s = 0.f;
    int base = b*16384 + chunk*256;
    for (int p = 0; p < 256; p++) s += __bfloat162float(cv2b[(size_t)(base + p)*Cc + c]);
    pp[blk*Cc + c] = s;
}

__global__ void ca_kernel(const float* __restrict__ pp,
                          const float* __restrict__ w1, const float* __restrict__ b1,
                          const float* __restrict__ w2, const float* __restrict__ b2,
                          float* __restrict__ ca) {
    __shared__ float pooled[Bc*Cc];
    __shared__ float t1[Bc*6];
    int tid = threadIdx.x;
    for (int i = tid; i < Bc*Cc; i += 256) {
        int b = i / Cc, c = i % Cc;
        float s = 0.f;
        for (int j = 0; j < 64; j++) s += pp[(b*64 + j)*Cc + c];
        pooled[i] = s * (1.f/16384.f);
    }
    __syncthreads();
    if (tid < Bc*6) {
        int b = tid / 6, j = tid % 6;
        float s = b1[j];
        for (int c = 0; c < Cc; c++) s += pooled[b*Cc + c] * w1[c*6 + j];
        t1[tid] = fmaxf(s, 0.f);
    }
    __syncthreads();
    for (int i = tid; i < Bc*Cc; i += 256) {
        int b = i / Cc, c = i % Cc;
        float s = b2[c];
        #pragma unroll
        for (int j = 0; j < 6; j++) s += t1[b*6 + j] * w2[j*Cc + c];
        ca[i] = 1.f / (1.f + expf(-s));
    }
}

// ---------------- flash window attention via tensor-core MMA ------------------
__global__ __launch_bounds__(256) void attn_mma(
        const bf16* __restrict__ qkvb, const bf16* __restrict__ btb,
        bf16* __restrict__ out) {
    extern __shared__ __align__(16) bf16 smA[];
    bf16* Qs = smA;
    bf16* Ks = smA + 256*QP;
    bf16* Vs = smA + 2*256*QP;
    int win = blockIdx.x, h = blockIdx.y;
    int tid = threadIdx.x;
    int warp = tid >> 5, lane = tid & 31;
    int g = lane >> 2, tg = lane & 3;
    int m0 = warp * 32;

    {
        const uint4* src = (const uint4*)(qkvb + (size_t)(win*Nc + tid)*576 + h*HDc);
        uint4* qd = (uint4*)(Qs + tid*QP);
        uint4* kd = (uint4*)(Ks + tid*QP);
        uint4* vd = (uint4*)(Vs + tid*QP);
        #pragma unroll
        for (int i = 0; i < 4; i++) {
            qd[i] = src[i];
            kd[i] = src[i + 24];
            vd[i] = src[i + 48];
        }
    }
    __syncthreads();

    uint32_t qf[2][2][4];
    #pragma unroll
    for (int mi = 0; mi < 2; mi++)
        #pragma unroll
        for (int ks = 0; ks < 2; ks++) {
            int r = m0 + mi*16 + (lane & 15);
            int kofs = ks*16 + ((lane >> 4) << 3);
            ldsm4(qf[mi][ks], (uint32_t)__cvta_generic_to_shared(Qs + r*QP + kofs));
        }

    const bf16* cb = btb + ((size_t)h << 16);

    int wl = win & 63;
    bool er = (wl >> 3) == 7, ec = (wl & 7) == 7;
    bool edge = er || ec;
    int lq[2][2];
    #pragma unroll
    for (int mi = 0; mi < 2; mi++)
        #pragma unroll
        for (int rh = 0; rh < 2; rh++) {
            int q = m0 + mi*16 + g + rh*8;
            int rc = er ? (((q >> 4) < 8) ? 1 : 2) : 0;
            int cc = ec ? (((q & 15) < 8) ? 1 : 2) : 0;
            lq[mi][rh] = rc*3 + cc;
        }

    float mx[2][2], lsum[2][2];
    float o[2][4][4];
    #pragma unroll
    for (int mi = 0; mi < 2; mi++)
        #pragma unroll
        for (int rh = 0; rh < 2; rh++) { mx[mi][rh] = -1e30f; lsum[mi][rh] = 0.f; }
    #pragma unroll
    for (int mi = 0; mi < 2; mi++)
        #pragma unroll
        for (int nt = 0; nt < 4; nt++)
            #pragma unroll
            for (int e = 0; e < 4; e++) o[mi][nt][e] = 0.f;

    for (int c0 = 0; c0 < Nc; c0 += 32) {
        float s[2][4][4];
        #pragma unroll
        for (int mi = 0; mi < 2; mi++)
            #pragma unroll
            for (int nj = 0; nj < 4; nj++)
                #pragma unroll
                for (int e = 0; e < 4; e++) s[mi][nj][e] = 0.f;

        #pragma unroll
        for (int ks = 0; ks < 2; ks++) {
            uint32_t kf[2][4];
            #pragma unroll
            for (int np = 0; np < 2; np++) {
                int n = c0 + np*16 + (lane & 7) + ((lane >> 4) << 3);
                int kc = ks*16 + ((lane >> 3) & 1)*8;
                ldsm4(kf[np], (uint32_t)__cvta_generic_to_shared(Ks + n*QP + kc));
            }
            #pragma unroll
            for (int mi = 0; mi < 2; mi++) {
                mma_bf16(s[mi][0], qf[mi][ks], &kf[0][0]);
                mma_bf16(s[mi][1], qf[mi][ks], &kf[0][2]);
                mma_bf16(s[mi][2], qf[mi][ks], &kf[1][0]);
                mma_bf16(s[mi][3], qf[mi][ks], &kf[1][2]);
            }
        }

        int lk[4][2];
        if (edge) {
            #pragma unroll
            for (int nj = 0; nj < 4; nj++)
                #pragma unroll
                for (int e = 0; e < 2; e++) {
                    int kcol = c0 + nj*8 + tg*2 + e;
                    int rc = er ? (((kcol >> 4) < 8) ? 1 : 2) : 0;
                    int cc = ec ? (((kcol & 15) < 8) ? 1 : 2) : 0;
                    lk[nj][e] = rc*3 + cc;
                }
        }
        #pragma unroll
        for (int mi = 0; mi < 2; mi++) {
            int row0 = m0 + mi*16 + g;
            #pragma unroll
            for (int nj = 0; nj < 4; nj++) {
                int col = c0 + nj*8 + tg*2;
                float2 b0 = __bfloat1622float2(*(const __nv_bfloat162*)(cb + (size_t)row0*Nc + col));
                float2 b1 = __bfloat1622float2(*(const __nv_bfloat162*)(cb + (size_t)(row0+8)*Nc + col));
                s[mi][nj][0] = s[mi][nj][0]*ATT_SCALE + b0.x;
                s[mi][nj][1] = s[mi][nj][1]*ATT_SCALE + b0.y;
                s[mi][nj][2] = s[mi][nj][2]*ATT_SCALE + b1.x;
                s[mi][nj][3] = s[mi][nj][3]*ATT_SCALE + b1.y;
                if (edge) {
                    s[mi][nj][0] += (lq[mi][0] == lk[nj][0]) ? 0.f : -100.f;
                    s[mi][nj][1] += (lq[mi][0] == lk[nj][1]) ? 0.f : -100.f;
                    s[mi][nj][2] += (lq[mi][1] == lk[nj][0]) ? 0.f : -100.f;
                    s[mi][nj][3] += (lq[mi][1] == lk[nj][1]) ? 0.f : -100.f;
                }
            }
            #pragma unroll
            for (int rh = 0; rh < 2; rh++) {
                int e0 = rh*2;
                float m_ = fmaxf(fmaxf(s[mi][0][e0], s[mi][0][e0+1]),
                                 fmaxf(s[mi][1][e0], s[mi][1][e0+1]));
                m_ = fmaxf(m_, fmaxf(fmaxf(s[mi][2][e0], s[mi][2][e0+1]),
                                     fmaxf(s[mi][3][e0], s[mi][3][e0+1])));
                m_ = fmaxf(m_, __shfl_xor_sync(0xffffffffu, m_, 1));
                m_ = fmaxf(m_, __shfl_xor_sync(0xffffffffu, m_, 2));
                float newm = fmaxf(mx[mi][rh], m_);
                float sc = __expf(mx[mi][rh] - newm);
                mx[mi][rh] = newm;
                float ps = 0.f;
                #pragma unroll
                for (int nj = 0; nj < 4; nj++) {
                    float p0 = __expf(s[mi][nj][e0]   - newm);
                    float p1 = __expf(s[mi][nj][e0+1] - newm);
                    s[mi][nj][e0] = p0; s[mi][nj][e0+1] = p1;
                    ps += p0 + p1;
                }
                ps += __shfl_xor_sync(0xffffffffu, ps, 1);
                ps += __shfl_xor_sync(0xffffffffu, ps, 2);
                lsum[mi][rh] = lsum[mi][rh]*sc + ps;
                #pragma unroll
                for (int nt = 0; nt < 4; nt++) {
                    o[mi][nt][e0]   *= sc;
                    o[mi][nt][e0+1] *= sc;
                }
            }
        }

        #pragma unroll
        for (int ks2 = 0; ks2 < 2; ks2++) {
            uint32_t vf[2][4];
            int krow = c0 + ks2*16 + (lane & 7) + (lane & 8);
            #pragma unroll
            for (int dp = 0; dp < 2; dp++)
                ldsm4t(vf[dp], (uint32_t)__cvta_generic_to_shared(
                    Vs + krow*QP + dp*16 + ((lane >> 4) << 3)));
            #pragma unroll
            for (int mi = 0; mi < 2; mi++) {
                uint32_t af[4];
                af[0] = pkbf2(s[mi][2*ks2][0],   s[mi][2*ks2][1]);
                af[1] = pkbf2(s[mi][2*ks2][2],   s[mi][2*ks2][3]);
                af[2] = pkbf2(s[mi][2*ks2+1][0], s[mi][2*ks2+1][1]);
                af[3] = pkbf2(s[mi][2*ks2+1][2], s[mi][2*ks2+1][3]);
                mma_bf16(o[mi][0], af, &vf[0][0]);
                mma_bf16(o[mi][1], af, &vf[0][2]);
                mma_bf16(o[mi][2], af, &vf[1][0]);
                mma_bf16(o[mi][3], af, &vf[1][2]);
            }
        }
    }

    #pragma unroll
    for (int mi = 0; mi < 2; mi++) {
        #pragma unroll
        for (int rh = 0; rh < 2; rh++) {
            float inv = 1.f / lsum[mi][rh];
            int row = win*Nc + m0 + mi*16 + g + rh*8;
            bf16* orow = out + (size_t)row*Cc + h*HDc;
            #pragma unroll
            for (int nt = 0; nt < 4; nt++) {
                *(__nv_bfloat162*)(orow + nt*8 + tg*2) =
                    __floats2bfloat162_rn(o[mi][nt][rh*2]*inv, o[mi][nt][rh*2+1]*inv);
            }
        }
    }
}

// ---------------- launch -----------------------------------------------------
extern "C" void kernel_launch(void* const* d_in, const int* in_sizes, int n_in,
                              void* d_out, int out_size) {
    const float* x     = (const float*)d_in[0];
    const float* qkv_w = (const float*)d_in[1];
    const float* qkv_b = (const float*)d_in[2];
    const float* proj_w= (const float*)d_in[3];
    const float* proj_b= (const float*)d_in[4];
    const float* rpb   = (const float*)d_in[5];
    const float* n1w   = (const float*)d_in[6];
    const float* n1b   = (const float*)d_in[7];
    const float* n2w   = (const float*)d_in[8];
    const float* n2b   = (const float*)d_in[9];
    const float* c1w   = (const float*)d_in[10];
    const float* c1b   = (const float*)d_in[11];
    const float* c2w   = (const float*)d_in[12];
    const float* c2b   = (const float*)d_in[13];
    const float* ca1w  = (const float*)d_in[14];
    const float* ca1b  = (const float*)d_in[15];
    const float* ca2w  = (const float*)d_in[16];
    const float* ca2b  = (const float*)d_in[17];
    const float* fc1w  = (const float*)d_in[18];
    const float* fc1b  = (const float*)d_in[19];
    const float* fc2w  = (const float*)d_in[20];
    const float* fc2b  = (const float*)d_in[21];
    const int*   rpi   = (const int*)d_in[22];
    float* out = (float*)d_out;

    bf16 *xnb, *qkvb, *atb, *cv1b, *cv2b, *ynb, *hb, *btb;
    bf16 *wqkv, *wproj, *wfc1, *wfc2, *wc1, *wc2;
    float *y, *pp, *cab;
    cudaGetSymbolAddress((void**)&xnb,  g_xnb);
    cudaGetSymbolAddress((void**)&qkvb, g_qkvb);
    cudaGetSymbolAddress((void**)&atb,  g_atb);
    cudaGetSymbolAddress((void**)&cv1b, g_cv1b);
    cudaGetSymbolAddress((void**)&cv2b, g_cv2b);
    cudaGetSymbolAddress((void**)&y,    g_y);
    cudaGetSymbolAddress((void**)&ynb,  g_ynb);
    cudaGetSymbolAddress((void**)&hb,   g_hb);
    cudaGetSymbolAddress((void**)&pp,   g_pp);
    cudaGetSymbolAddress((void**)&cab,  g_ca);
    cudaGetSymbolAddress((void**)&btb,  g_btb);
    cudaGetSymbolAddress((void**)&wqkv, g_wqkv);
    cudaGetSymbolAddress((void**)&wproj,g_wproj);
    cudaGetSymbolAddress((void**)&wfc1, g_wfc1);
    cudaGetSymbolAddress((void**)&wfc2, g_wfc2);
    cudaGetSymbolAddress((void**)&wc1,  g_wc1);
    cudaGetSymbolAddress((void**)&wc2,  g_wc2);

    static cudaStream_t sB = nullptr;
    static cudaEvent_t evF = nullptr, evL = nullptr, evW = nullptr, evB = nullptr;
    if (!sB) {
        cudaStreamCreateWithFlags(&sB, cudaStreamNonBlocking);
        cudaEventCreateWithFlags(&evF, cudaEventDisableTiming);
        cudaEventCreateWithFlags(&evL, cudaEventDisableTiming);
        cudaEventCreateWithFlags(&evW, cudaEventDisableTiming);
        cudaEventCreateWithFlags(&evB, cudaEventDisableTiming);
        cudaFuncSetAttribute(attn_mma, cudaFuncAttributeMaxDynamicSharedMemorySize,
                             3*256*QP*sizeof(bf16));
    }

    // fork sB into the capture FIRST (event from capturing stream)
    cudaEventRecord(evF, 0);
    cudaStreamWaitEvent(sB, evF, 0);

    // prologue: weight converts on sB, LN1 on main (independent)
    f2b_all<<<(STOT + 255)/256, 256, 0, sB>>>(qkv_w, proj_w, fc1w, fc2w, c1w, c2w,
                                              wqkv, wproj, wfc1, wfc2, wc1, wc2);
    btb_kernel<<<NHc*Nc*Nc/256, 256, 0, sB>>>(rpb, rpi, btb);
    cudaEventRecord(evW, sB);                 // weights + bias table ready

    ln_kernel<<<NPIX/8, 256>>>(x, n1w, n1b, xnb);
    cudaEventRecord(evL, 0);                  // xnb ready

    // conv branch on sB (needs xnb from main; wc1/wc2 already sB-ordered)
    cudaStreamWaitEvent(sB, evL, 0);
    mma_conv<1, Cc, 64><<<dim3(Bc*Hc, 1), 256, 0, sB>>>(xnb, wc1, c1b, cv1b);
    mma_conv<0, 64, Cc><<<dim3(Bc*Hc, 3), 256, 0, sB>>>(cv1b, wc2, c2b, cv2b);
    pool_kernel<<<Bc*64, Cc, 0, sB>>>(cv2b, pp);
    ca_kernel<<<1, 256, 0, sB>>>(pp, ca1w, ca1b, ca2w, ca2b, cab);
    cudaEventRecord(evB, sB);

    // attention branch on main (needs wqkv/btb from sB)
    cudaStreamWaitEvent(0, evW, 0);
    mma_gemm<0, 1, Cc, 3*Cc><<<dim3(NPIX/128, 9), 256>>>(xnb, wqkv, qkv_b, qkvb,
                                                         nullptr, nullptr, nullptr, nullptr);
    attn_mma<<<dim3(256, NHc), 256, 3*256*QP*sizeof(bf16)>>>(qkvb, btb, atb);

    // join: proj + window-reverse + residual combine needs conv branch
    cudaStreamWaitEvent(0, evB, 0);
    mma_gemm<3, 0, Cc, Cc><<<dim3(NPIX/128, 3), 256>>>(atb, wproj, proj_b, y,
                                                       nullptr, x, cv2b, cab);
    // MLP
    ln_kernel<<<NPIX/8, 256>>>(y, n2w, n2b, ynb);
    mma_gemm<1, 0, Cc, 4*Cc><<<dim3(NPIX/128, 12), 256>>>(ynb, wfc1, fc1b, hb,
                                                          nullptr, nullptr, nullptr, nullptr);
    mma_gemm<2, 0, 4*Cc, Cc><<<dim3(NPIX/128, 3), 256>>>(hb, wfc2, fc2b, out,
                                                         y, nullptr, nullptr, nullptr);
}